// round 1
// baseline (speedup 1.0000x reference)
#include <cuda_runtime.h>
#include <math.h>

#define BB 8
#define NN 4096
#define DIM 512
#define HEADS 8
#define DHEAD 64
#define DINNER 512          // HEADS*DHEAD
#define BH (BB*HEADS)       // 64

// -------- scratch (static device globals; allocation-free) --------
__device__ float g_q[BB * DINNER * NN];       // [b][h*64+d][n]  64MB
__device__ float g_k[BB * DINNER * NN];       // 64MB
__device__ float g_v[BB * DINNER * NN];       // 64MB
__device__ float g_rnorm[BB * NN];            // sqrt(512)/||x_row||
__device__ float g_invnq[BH * DHEAD];         // 1/||q_{b,h,d,:}||
__device__ float g_invnk[BH * DHEAD];
__device__ float g_gpart[BH * 8 * DHEAD * DHEAD];   // split-K partials of q·k
__device__ float g_attn[BH * DHEAD * DHEAD];        // softmax result
__device__ float g_attnw[BB * DINNER * DIM];        // folded attn^T @ w_out

// -------- K1: per-row RMSNorm scale: rnorm = sqrt(512)/max(||x||,1e-12) ----
__global__ void k_rnorm(const float* __restrict__ x) {
    int row = blockIdx.x;                  // 0..32767
    const float4 v = ((const float4*)(x + (size_t)row * DIM))[threadIdx.x];
    float s = v.x*v.x + v.y*v.y + v.z*v.z + v.w*v.w;
    #pragma unroll
    for (int o = 16; o; o >>= 1) s += __shfl_xor_sync(0xffffffffu, s, o);
    __shared__ float ws[4];
    if ((threadIdx.x & 31) == 0) ws[threadIdx.x >> 5] = s;
    __syncthreads();
    if (threadIdx.x == 0) {
        float t = ws[0] + ws[1] + ws[2] + ws[3];
        g_rnorm[row] = 22.62741699796952f / fmaxf(sqrtf(t), 1e-12f);
    }
}

// -------- K2: QKV GEMM (xn @ w_qkv), writes q/k/v transposed [b][hd][n] ----
// 128x128 tile, BK=8, 256 threads, 8x8 microtile (strided mapping).
__global__ __launch_bounds__(256) void k_qkv(const float* __restrict__ x,
                                             const float* __restrict__ gamma,
                                             const float* __restrict__ w_qkv) {
    __shared__ float As[8][128];   // [k][m]
    __shared__ float Bs[8][128];   // [k][c]
    const int tid = threadIdx.x;
    const int m0 = blockIdx.x * 128;
    const int c0 = blockIdx.y * 128;
    const int a_m = tid >> 1, a_k = (tid & 1) * 4;
    const int b_k = tid >> 5, b_c = (tid & 31) * 4;
    const int row_t = tid & 15;    // m fast -> n-coalesced epilogue
    const int col_t = tid >> 4;
    const float rs = g_rnorm[m0 + a_m];
    float acc[8][8];
    #pragma unroll
    for (int i = 0; i < 8; i++)
        #pragma unroll
        for (int j = 0; j < 8; j++) acc[i][j] = 0.f;

    for (int k0 = 0; k0 < DIM; k0 += 8) {
        float4 xa = *(const float4*)(x + (size_t)(m0 + a_m) * DIM + k0 + a_k);
        float4 g4 = *(const float4*)(gamma + k0 + a_k);
        As[a_k + 0][a_m] = xa.x * rs * g4.x;
        As[a_k + 1][a_m] = xa.y * rs * g4.y;
        As[a_k + 2][a_m] = xa.z * rs * g4.z;
        As[a_k + 3][a_m] = xa.w * rs * g4.w;
        *(float4*)&Bs[b_k][b_c] =
            *(const float4*)(w_qkv + (size_t)(k0 + b_k) * 1536 + c0 + b_c);
        __syncthreads();
        #pragma unroll
        for (int kk = 0; kk < 8; kk++) {
            float a[8], bb[8];
            #pragma unroll
            for (int i = 0; i < 8; i++) a[i] = As[kk][row_t + 16 * i];
            #pragma unroll
            for (int j = 0; j < 8; j++) bb[j] = Bs[kk][col_t + 16 * j];
            #pragma unroll
            for (int i = 0; i < 8; i++)
                #pragma unroll
                for (int j = 0; j < 8; j++) acc[i][j] += a[i] * bb[j];
        }
        __syncthreads();
    }
    const int bidx = m0 >> 12;       // /4096
    const int nbase = m0 & 4095;
    #pragma unroll
    for (int j = 0; j < 8; j++) {
        int c = c0 + col_t + 16 * j;
        int which = c >> 9;
        int hd = c & 511;
        float* outp = (which == 0) ? g_q : (which == 1) ? g_k : g_v;
        size_t base = ((size_t)bidx * DINNER + hd) * NN + nbase;
        #pragma unroll
        for (int i = 0; i < 8; i++) outp[base + row_t + 16 * i] = acc[i][j];
    }
}

// -------- K3: 1/||row|| over n for q and k --------
__global__ void k_rownorm() {
    int row = blockIdx.x;              // 0..8191 (q rows then k rows)
    const float* p = ((row < 4096) ? g_q : g_k) + (size_t)(row & 4095) * NN;
    int tid = threadIdx.x;
    float s = 0.f;
    #pragma unroll
    for (int t = 0; t < 4; t++) {
        float4 v = *(const float4*)(p + tid * 4 + t * 1024);
        s += v.x*v.x + v.y*v.y + v.z*v.z + v.w*v.w;
    }
    #pragma unroll
    for (int o = 16; o; o >>= 1) s += __shfl_xor_sync(0xffffffffu, s, o);
    __shared__ float ws[8];
    if ((tid & 31) == 0) ws[tid >> 5] = s;
    __syncthreads();
    if (tid == 0) {
        float t = 0.f;
        #pragma unroll
        for (int i = 0; i < 8; i++) t += ws[i];
        float inv = 1.0f / fmaxf(sqrtf(t), 1e-12f);
        if (row < 4096) g_invnq[row] = inv; else g_invnk[row & 4095] = inv;
    }
}

// -------- K4: sim partials: G[bh][d][e] += sum_n q*k over a 512-wide n slice
__global__ __launch_bounds__(256) void k_simpart() {
    const int bh = blockIdx.x;   // 64
    const int sp = blockIdx.y;   // 8 splits of n
    __shared__ float Qs[64][65];
    __shared__ float Ks[64][65];
    const int tid = threadIdx.x;
    const int d_t = tid >> 4, e_t = tid & 15;
    const float* qb = g_q + (size_t)bh * DHEAD * NN + sp * 512;
    const float* kb = g_k + (size_t)bh * DHEAD * NN + sp * 512;
    float acc[4][4];
    #pragma unroll
    for (int i = 0; i < 4; i++)
        #pragma unroll
        for (int j = 0; j < 4; j++) acc[i][j] = 0.f;

    for (int n0 = 0; n0 < 512; n0 += 64) {
        #pragma unroll
        for (int t = 0; t < 16; t++) {
            int idx = tid + 256 * t;
            int d = idx >> 6, nn = idx & 63;
            Qs[d][nn] = qb[(size_t)d * NN + n0 + nn];
            Ks[d][nn] = kb[(size_t)d * NN + n0 + nn];
        }
        __syncthreads();
        #pragma unroll 8
        for (int nn = 0; nn < 64; nn++) {
            float qv[4], kv[4];
            #pragma unroll
            for (int i = 0; i < 4; i++) qv[i] = Qs[d_t + 16 * i][nn];
            #pragma unroll
            for (int j = 0; j < 4; j++) kv[j] = Ks[e_t + 16 * j][nn];
            #pragma unroll
            for (int i = 0; i < 4; i++)
                #pragma unroll
                for (int j = 0; j < 4; j++) acc[i][j] += qv[i] * kv[j];
        }
        __syncthreads();
    }
    float* gp = g_gpart + ((size_t)bh * 8 + sp) * 4096;
    #pragma unroll
    for (int i = 0; i < 4; i++)
        #pragma unroll
        for (int j = 0; j < 4; j++)
            gp[(d_t + 16 * i) * 64 + (e_t + 16 * j)] = acc[i][j];
}

// -------- K5: reduce partials, scale (norms * exp(T) * 8), softmax over e ---
__global__ void k_softmax(const float* __restrict__ temperature) {
    const int bh = blockIdx.x;     // 64
    const int d = threadIdx.x;     // 64
    const int h = bh & 7;
    const float sc = 8.0f * expf(temperature[h]) * g_invnq[bh * 64 + d];
    const float* gp = g_gpart + (size_t)bh * 8 * 4096;
    float vals[64];
    float mx = -1e30f;
    #pragma unroll 4
    for (int e = 0; e < 64; e++) {
        float s = 0.f;
        #pragma unroll
        for (int sp = 0; sp < 8; sp++) s += gp[sp * 4096 + d * 64 + e];
        s *= sc * g_invnk[bh * 64 + e];
        vals[e] = s;
        mx = fmaxf(mx, s);
    }
    float sum = 0.f;
    #pragma unroll 4
    for (int e = 0; e < 64; e++) { vals[e] = expf(vals[e] - mx); sum += vals[e]; }
    const float inv = 1.0f / sum;
    #pragma unroll 4
    for (int e = 0; e < 64; e++)
        g_attn[(size_t)bh * 4096 + d * 64 + e] = vals[e] * inv;
}

// -------- K6: fold attn into w_out: attnW[b][(h,e)][j] = sum_d A[d][e]*w_out[h*64+d][j]
__global__ __launch_bounds__(256) void k_attnw(const float* __restrict__ w_out) {
    const int bh = blockIdx.x;     // 64
    const int jt = blockIdx.y;     // 4
    const int b = bh >> 3, h = bh & 7;
    __shared__ float As[64][64];   // A[d][e]
    const int tid = threadIdx.x;
    #pragma unroll
    for (int t = 0; t < 16; t++) {
        int idx = tid + 256 * t;
        As[idx >> 6][idx & 63] = g_attn[(size_t)bh * 4096 + idx];
    }
    __syncthreads();
    const int j = jt * 128 + (tid & 127);
    const int e0 = (tid >> 7) * 32;
    float acc[32];
    #pragma unroll
    for (int i = 0; i < 32; i++) acc[i] = 0.f;
    for (int d = 0; d < 64; d++) {
        float w = w_out[(h * 64 + d) * DIM + j];
        #pragma unroll
        for (int i = 0; i < 32; i++) acc[i] += As[d][e0 + i] * w;
    }
    #pragma unroll
    for (int i = 0; i < 32; i++)
        g_attnw[((size_t)b * DINNER + h * 64 + e0 + i) * DIM + j] = acc[i];
}

// -------- K7: final GEMM per b: out[n][j] = sum_c V[b][c][n] * attnW[b][c][j]
__global__ __launch_bounds__(256) void k_final(float* __restrict__ out) {
    const int b = blockIdx.z;
    const int n0 = blockIdx.x * 128;
    const int j0 = blockIdx.y * 128;
    __shared__ float As[8][128];   // [c][n]
    __shared__ float Bs[8][128];   // [c][j]
    const int tid = threadIdx.x;
    const int a_c = tid >> 5, a_n = (tid & 31) * 4;
    const int row_t = tid >> 4;    // n group
    const int col_t = tid & 15;    // j fast -> coalesced output
    const float* vb = g_v + (size_t)b * DINNER * NN;
    const float* wb = g_attnw + (size_t)b * DINNER * DIM;
    float acc[8][8];
    #pragma unroll
    for (int i = 0; i < 8; i++)
        #pragma unroll
        for (int j = 0; j < 8; j++) acc[i][j] = 0.f;

    for (int c0 = 0; c0 < DINNER; c0 += 8) {
        *(float4*)&As[a_c][a_n] =
            *(const float4*)(vb + (size_t)(c0 + a_c) * NN + n0 + a_n);
        *(float4*)&Bs[a_c][a_n] =
            *(const float4*)(wb + (size_t)(c0 + a_c) * DIM + j0 + a_n);
        __syncthreads();
        #pragma unroll
        for (int kk = 0; kk < 8; kk++) {
            float a[8], bv[8];
            #pragma unroll
            for (int i = 0; i < 8; i++) a[i] = As[kk][row_t + 16 * i];
            #pragma unroll
            for (int j = 0; j < 8; j++) bv[j] = Bs[kk][col_t + 16 * j];
            #pragma unroll
            for (int i = 0; i < 8; i++)
                #pragma unroll
                for (int j = 0; j < 8; j++) acc[i][j] += a[i] * bv[j];
        }
        __syncthreads();
    }
    float* ob = out + (size_t)b * NN * DIM;
    #pragma unroll
    for (int i = 0; i < 8; i++) {
        int n = n0 + row_t + 16 * i;
        #pragma unroll
        for (int j = 0; j < 8; j++)
            ob[(size_t)n * DIM + j0 + col_t + 16 * j] = acc[i][j];
    }
}

// -------- launch --------
extern "C" void kernel_launch(void* const* d_in, const int* in_sizes, int n_in,
                              void* d_out, int out_size) {
    const float* x           = (const float*)d_in[0];
    const float* gamma       = (const float*)d_in[1];
    const float* w_qkv       = (const float*)d_in[2];
    const float* temperature = (const float*)d_in[3];
    const float* w_out       = (const float*)d_in[4];
    float* out = (float*)d_out;

    k_rnorm  <<<BB * NN, 128>>>(x);
    k_qkv    <<<dim3(256, 12), 256>>>(x, gamma, w_qkv);
    k_rownorm<<<2 * BH * DHEAD, 256>>>();
    k_simpart<<<dim3(BH, 8), 256>>>();
    k_softmax<<<BH, 64>>>(temperature);
    k_attnw  <<<dim3(BH, 4), 256>>>(w_out);
    k_final  <<<dim3(32, 4, BB), 256>>>(out);
}

// round 4
// speedup vs baseline: 2.6867x; 2.6867x over previous
#include <cuda_runtime.h>
#include <cuda_bf16.h>
#include <math.h>
#include <stdint.h>

#define BB 8
#define NN 4096
#define DIM 512
#define HEADS 8
#define DHEAD 64
#define DINNER 512
#define BH (BB*HEADS)       // 64

// ---------------- scratch (static device globals) ----------------
__device__ float g_q[BB*DINNER*NN];                  // [b][hd][n] fp32
__device__ float g_k[BB*DINNER*NN];                  // [b][hd][n] fp32
__device__ __nv_bfloat16 g_vhi[(size_t)BB*NN*DINNER];// [b][n][c]
__device__ __nv_bfloat16 g_vlo[(size_t)BB*NN*DINNER];
__device__ __nv_bfloat16 g_xhi[(size_t)BB*NN*DIM];   // normalized x, [m][k]
__device__ __nv_bfloat16 g_xlo[(size_t)BB*NN*DIM];
__device__ __nv_bfloat16 g_whi[1536*DIM];            // w_qkv^T, [c][k]
__device__ __nv_bfloat16 g_wlo[1536*DIM];
__device__ __nv_bfloat16 g_awhi[(size_t)BB*DIM*DINNER]; // attn-folded w_out^T, [b][j][c]
__device__ __nv_bfloat16 g_awlo[(size_t)BB*DIM*DINNER];
__device__ float g_invnq[BH*DHEAD];
__device__ float g_invnk[BH*DHEAD];
__device__ float g_gpart[BH*8*DHEAD*DHEAD];
__device__ float g_attn[BH*DHEAD*DHEAD];

// ---------------- helpers ----------------
__device__ __forceinline__ uint32_t smem_u32(const void* p) {
    uint32_t a;
    asm("{ .reg .u64 t; cvta.to.shared.u64 t, %1; cvt.u32.u64 %0, t; }" : "=r"(a) : "l"(p));
    return a;
}
__device__ __forceinline__ uint32_t sw128(uint32_t o) { return o ^ ((o >> 3) & 0x70); }

__device__ __forceinline__ void ldsm4(uint32_t* r, uint32_t addr) {
    asm volatile("ldmatrix.sync.aligned.m8n8.x4.shared.b16 {%0,%1,%2,%3}, [%4];"
                 : "=r"(r[0]), "=r"(r[1]), "=r"(r[2]), "=r"(r[3]) : "r"(addr));
}
__device__ __forceinline__ void mma16816(float* d, const uint32_t* a, const uint32_t* b) {
    asm volatile("mma.sync.aligned.m16n8k16.row.col.f32.bf16.bf16.f32 "
                 "{%0,%1,%2,%3}, {%4,%5,%6,%7}, {%8,%9}, {%0,%1,%2,%3};"
                 : "+f"(d[0]), "+f"(d[1]), "+f"(d[2]), "+f"(d[3])
                 : "r"(a[0]), "r"(a[1]), "r"(a[2]), "r"(a[3]), "r"(b[0]), "r"(b[1]));
}

__device__ __forceinline__ void split2(float a, float b, uint32_t& hi, uint32_t& lo) {
    __nv_bfloat16 ha = __float2bfloat16(a), hb = __float2bfloat16(b);
    __nv_bfloat16 la = __float2bfloat16(a - __bfloat162float(ha));
    __nv_bfloat16 lb = __float2bfloat16(b - __bfloat162float(hb));
    hi = (uint32_t)*reinterpret_cast<unsigned short*>(&ha) |
         ((uint32_t)*reinterpret_cast<unsigned short*>(&hb) << 16);
    lo = (uint32_t)*reinterpret_cast<unsigned short*>(&la) |
         ((uint32_t)*reinterpret_cast<unsigned short*>(&lb) << 16);
}

// smem: 4 tiles of [128 rows][64 bf16] = 16KB each, SW128-swizzled (128B rows)
#define SM_AHI 0
#define SM_ALO 16384
#define SM_BHI 32768
#define SM_BLO 49152
#define SMEM_BYTES 65536

// mainloop: acc[4][4][4] += split-bf16(A[128x512]) * split-bf16(B[128x512])^T
// 8 warps: warp grid 2(m) x 4(n); warp tile 64m x 32n; K chunks of 64.
__device__ __forceinline__ void mma_mainloop(char* smem,
        const __nv_bfloat16* __restrict__ Ahi, const __nv_bfloat16* __restrict__ Alo,
        const __nv_bfloat16* __restrict__ Bhi, const __nv_bfloat16* __restrict__ Blo,
        float acc[4][4][4]) {
    const int tid = threadIdx.x;
    const int wid = tid >> 5, lane = tid & 31;
    const int wm = wid >> 2, wn = wid & 3;
    const int g = lane >> 3, lr = lane & 7;
    const uint32_t sb = smem_u32(smem);

    // precomputed ldmatrix base offsets (c16 part added per k-step)
    const int a_row = wm * 64 + lr + (g & 1) * 8;   // + mi*16
    const int a_c16 = (g >> 1);                     // + ks*2
    const int b_row = wn * 32 + lr + (g >> 1) * 8;  // + nj*16
    const int b_c16 = (g & 1);                      // + ks*2

    for (int ch = 0; ch < 8; ch++) {
        #pragma unroll
        for (int it = 0; it < 4; it++) {
            int idx = tid + 256 * it;
            int row = idx >> 3, c16 = idx & 7;
            uint32_t so = sw128((uint32_t)(row * 128 + c16 * 16));
            size_t go = (size_t)row * 512 + ch * 64 + c16 * 8;
            *(uint4*)(smem + SM_AHI + so) = *(const uint4*)(Ahi + go);
            *(uint4*)(smem + SM_ALO + so) = *(const uint4*)(Alo + go);
            *(uint4*)(smem + SM_BHI + so) = *(const uint4*)(Bhi + go);
            *(uint4*)(smem + SM_BLO + so) = *(const uint4*)(Blo + go);
        }
        __syncthreads();
        #pragma unroll
        for (int ks = 0; ks < 4; ks++) {
            uint32_t ah[4][4], al[4][4], bf[2][4];
            #pragma unroll
            for (int mi = 0; mi < 4; mi++) {
                uint32_t off = sw128((uint32_t)((a_row + mi * 16) * 128 +
                                                (a_c16 + ks * 2) * 16));
                ldsm4(ah[mi], sb + SM_AHI + off);
                ldsm4(al[mi], sb + SM_ALO + off);
            }
            #pragma unroll
            for (int nj = 0; nj < 2; nj++) {
                uint32_t off = sw128((uint32_t)((b_row + nj * 16) * 128 +
                                                (b_c16 + ks * 2) * 16));
                ldsm4(bf[nj], sb + SM_BHI + off);
            }
            #pragma unroll
            for (int mi = 0; mi < 4; mi++)
                #pragma unroll
                for (int nj = 0; nj < 4; nj++)
                    mma16816(acc[mi][nj], ah[mi], &bf[nj >> 1][(nj & 1) * 2]);
            #pragma unroll
            for (int mi = 0; mi < 4; mi++)
                #pragma unroll
                for (int nj = 0; nj < 4; nj++)
                    mma16816(acc[mi][nj], al[mi], &bf[nj >> 1][(nj & 1) * 2]);
            // reuse bf regs for B-lo
            #pragma unroll
            for (int nj = 0; nj < 2; nj++) {
                uint32_t off = sw128((uint32_t)((b_row + nj * 16) * 128 +
                                                (b_c16 + ks * 2) * 16));
                ldsm4(bf[nj], sb + SM_BLO + off);
            }
            #pragma unroll
            for (int mi = 0; mi < 4; mi++)
                #pragma unroll
                for (int nj = 0; nj < 4; nj++)
                    mma16816(acc[mi][nj], ah[mi], &bf[nj >> 1][(nj & 1) * 2]);
        }
        __syncthreads();
    }
}

// -------- K0a: fused RMSNorm + bf16 hi/lo split of activations ----
__global__ void k_prepA(const float* __restrict__ x, const float* __restrict__ gamma) {
    const int row = blockIdx.x;
    const int tid = threadIdx.x;
    const float4 v = ((const float4*)(x + (size_t)row * DIM))[tid];
    float s = v.x * v.x + v.y * v.y + v.z * v.z + v.w * v.w;
    #pragma unroll
    for (int o = 16; o; o >>= 1) s += __shfl_xor_sync(0xffffffffu, s, o);
    __shared__ float ws[4];
    __shared__ float rs_sh;
    if ((tid & 31) == 0) ws[tid >> 5] = s;
    __syncthreads();
    if (tid == 0)
        rs_sh = 22.62741699796952f / fmaxf(sqrtf(ws[0] + ws[1] + ws[2] + ws[3]), 1e-12f);
    __syncthreads();
    const float rs = rs_sh;
    const float4 g = ((const float4*)gamma)[tid];
    float a0 = v.x * rs * g.x, a1 = v.y * rs * g.y, a2 = v.z * rs * g.z, a3 = v.w * rs * g.w;
    uint2 ph, pl;
    split2(a0, a1, ph.x, pl.x);
    split2(a2, a3, ph.y, pl.y);
    ((uint2*)(g_xhi + (size_t)row * DIM))[tid] = ph;
    ((uint2*)(g_xlo + (size_t)row * DIM))[tid] = pl;
}

// -------- K0b: transpose + split w_qkv -> [c][k] hi/lo --------
__global__ void k_prepW(const float* __restrict__ w) {
    __shared__ float t[32][33];
    const int c0 = blockIdx.x * 32, k0 = blockIdx.y * 32;
    const int tx = threadIdx.x, ty = threadIdx.y;
    #pragma unroll
    for (int i = 0; i < 4; i++)
        t[ty + 8 * i][tx] = w[(size_t)(k0 + ty + 8 * i) * 1536 + c0 + tx];
    __syncthreads();
    #pragma unroll
    for (int i = 0; i < 4; i++) {
        float v = t[tx][ty + 8 * i];
        __nv_bfloat16 h = __float2bfloat16(v);
        __nv_bfloat16 l = __float2bfloat16(v - __bfloat162float(h));
        size_t o = (size_t)(c0 + ty + 8 * i) * 512 + k0 + tx;
        g_whi[o] = h;
        g_wlo[o] = l;
    }
}

// -------- QKV GEMM: D[m][c] = xn @ w_qkv via HMMA split-bf16 --------
__global__ __launch_bounds__(256, 2) void k_qkv_mma() {
    extern __shared__ char smem[];
    const int m0 = blockIdx.x * 128;
    const int c0 = blockIdx.y * 128;
    float acc[4][4][4];
    #pragma unroll
    for (int i = 0; i < 4; i++)
        #pragma unroll
        for (int j = 0; j < 4; j++)
            #pragma unroll
            for (int r = 0; r < 4; r++) acc[i][j][r] = 0.f;

    mma_mainloop(smem,
                 g_xhi + (size_t)m0 * 512, g_xlo + (size_t)m0 * 512,
                 g_whi + (size_t)c0 * 512, g_wlo + (size_t)c0 * 512, acc);

    const int tid = threadIdx.x;
    const int wid = tid >> 5, lane = tid & 31;
    const int wm = wid >> 2, wn = wid & 3;
    const int b = m0 >> 12;
    const int nbase = (m0 & 4095) + wm * 64 + (lane >> 2);
    const int cloc = wn * 32 + 2 * (lane & 3);
    const int which = c0 >> 9;          // 0:q 1:k 2:v (tile never straddles)
    const int cbase = (c0 & 511) + cloc;

    if (which < 2) {
        float* dst = (which ? g_k : g_q) + (size_t)b * DINNER * NN;
        #pragma unroll
        for (int mi = 0; mi < 4; mi++)
            #pragma unroll
            for (int nj = 0; nj < 4; nj++) {
                int c = cbase + nj * 8;
                #pragma unroll
                for (int h = 0; h < 2; h++) {
                    int n = nbase + mi * 16 + h * 8;
                    dst[(size_t)c * NN + n]       = acc[mi][nj][h * 2];
                    dst[(size_t)(c + 1) * NN + n] = acc[mi][nj][h * 2 + 1];
                }
            }
    } else {
        #pragma unroll
        for (int mi = 0; mi < 4; mi++)
            #pragma unroll
            for (int h = 0; h < 2; h++) {
                int n = nbase + mi * 16 + h * 8;
                size_t base = ((size_t)b * NN + n) * DINNER + cbase;
                #pragma unroll
                for (int nj = 0; nj < 4; nj++) {
                    uint32_t hi, lo;
                    split2(acc[mi][nj][h * 2], acc[mi][nj][h * 2 + 1], hi, lo);
                    *(uint32_t*)(g_vhi + base + nj * 8) = hi;
                    *(uint32_t*)(g_vlo + base + nj * 8) = lo;
                }
            }
    }
}

// -------- K3: 1/||row|| over n for q and k --------
__global__ void k_rownorm() {
    int row = blockIdx.x;
    const float* p = ((row < 4096) ? g_q : g_k) + (size_t)(row & 4095) * NN;
    int tid = threadIdx.x;
    float s = 0.f;
    #pragma unroll
    for (int t = 0; t < 4; t++) {
        float4 v = *(const float4*)(p + tid * 4 + t * 1024);
        s += v.x * v.x + v.y * v.y + v.z * v.z + v.w * v.w;
    }
    #pragma unroll
    for (int o = 16; o; o >>= 1) s += __shfl_xor_sync(0xffffffffu, s, o);
    __shared__ float ws[8];
    if ((tid & 31) == 0) ws[tid >> 5] = s;
    __syncthreads();
    if (tid == 0) {
        float t = 0.f;
        #pragma unroll
        for (int i = 0; i < 8; i++) t += ws[i];
        float inv = 1.0f / fmaxf(sqrtf(t), 1e-12f);
        if (row < 4096) g_invnq[row] = inv; else g_invnk[row & 4095] = inv;
    }
}

// -------- K4: sim partials over 512-wide n slices --------
__global__ __launch_bounds__(256) void k_simpart() {
    const int bh = blockIdx.x;
    const int sp = blockIdx.y;
    __shared__ float Qs[64][65];
    __shared__ float Ks[64][65];
    const int tid = threadIdx.x;
    const int d_t = tid >> 4, e_t = tid & 15;
    const float* qb = g_q + (size_t)bh * DHEAD * NN + sp * 512;
    const float* kb = g_k + (size_t)bh * DHEAD * NN + sp * 512;
    float acc[4][4];
    #pragma unroll
    for (int i = 0; i < 4; i++)
        #pragma unroll
        for (int j = 0; j < 4; j++) acc[i][j] = 0.f;

    for (int n0 = 0; n0 < 512; n0 += 64) {
        #pragma unroll
        for (int t = 0; t < 16; t++) {
            int idx = tid + 256 * t;
            int d = idx >> 6, nn = idx & 63;
            Qs[d][nn] = qb[(size_t)d * NN + n0 + nn];
            Ks[d][nn] = kb[(size_t)d * NN + n0 + nn];
        }
        __syncthreads();
        #pragma unroll 8
        for (int nn = 0; nn < 64; nn++) {
            float qv[4], kv[4];
            #pragma unroll
            for (int i = 0; i < 4; i++) qv[i] = Qs[d_t + 16 * i][nn];
            #pragma unroll
            for (int j = 0; j < 4; j++) kv[j] = Ks[e_t + 16 * j][nn];
            #pragma unroll
            for (int i = 0; i < 4; i++)
                #pragma unroll
                for (int j = 0; j < 4; j++) acc[i][j] += qv[i] * kv[j];
        }
        __syncthreads();
    }
    float* gp = g_gpart + ((size_t)bh * 8 + sp) * 4096;
    #pragma unroll
    for (int i = 0; i < 4; i++)
        #pragma unroll
        for (int j = 0; j < 4; j++)
            gp[(d_t + 16 * i) * 64 + (e_t + 16 * j)] = acc[i][j];
}

// -------- K5: reduce + scale + softmax --------
__global__ void k_softmax(const float* __restrict__ temperature) {
    const int bh = blockIdx.x;
    const int d = threadIdx.x;
    const int hh = bh & 7;
    const float sc = 8.0f * expf(temperature[hh]) * g_invnq[bh * 64 + d];
    const float* gp = g_gpart + (size_t)bh * 8 * 4096;
    float vals[64];
    float mx = -1e30f;
    #pragma unroll 4
    for (int e = 0; e < 64; e++) {
        float s = 0.f;
        #pragma unroll
        for (int sp = 0; sp < 8; sp++) s += gp[sp * 4096 + d * 64 + e];
        s *= sc * g_invnk[bh * 64 + e];
        vals[e] = s;
        mx = fmaxf(mx, s);
    }
    float sum = 0.f;
    #pragma unroll 4
    for (int e = 0; e < 64; e++) { vals[e] = expf(vals[e] - mx); sum += vals[e]; }
    const float inv = 1.0f / sum;
    #pragma unroll 4
    for (int e = 0; e < 64; e++)
        g_attn[(size_t)bh * 4096 + d * 64 + e] = vals[e] * inv;
}

// -------- K6: fold attn into w_out, write transposed hi/lo [b][j][c] --------
__global__ __launch_bounds__(256) void k_attnw(const float* __restrict__ w_out) {
    const int bh = blockIdx.x;
    const int jt = blockIdx.y;
    const int b = bh >> 3, hh = bh & 7;
    __shared__ float As[64][64];
    const int tid = threadIdx.x;
    #pragma unroll
    for (int t = 0; t < 16; t++) {
        int idx = tid + 256 * t;
        As[idx >> 6][idx & 63] = g_attn[(size_t)bh * 4096 + idx];
    }
    __syncthreads();
    const int j = jt * 128 + (tid & 127);
    const int e0 = (tid >> 7) * 32;
    float acc[32];
    #pragma unroll
    for (int i = 0; i < 32; i++) acc[i] = 0.f;
    for (int d = 0; d < 64; d++) {
        float w = w_out[(hh * 64 + d) * DIM + j];
        #pragma unroll
        for (int i = 0; i < 32; i++) acc[i] += As[d][e0 + i] * w;
    }
    size_t base = ((size_t)b * 512 + j) * 512 + hh * 64 + e0;
    #pragma unroll
    for (int i = 0; i < 32; i++) {
        __nv_bfloat16 h = __float2bfloat16(acc[i]);
        __nv_bfloat16 l = __float2bfloat16(acc[i] - __bfloat162float(h));
        g_awhi[base + i] = h;
        g_awlo[base + i] = l;
    }
}

// -------- final GEMM: out[b][n][j] = sum_c V[b][n][c] * aw[b][j][c] --------
__global__ __launch_bounds__(256, 2) void k_final_mma(float* __restrict__ out) {
    extern __shared__ char smem[];
    const int m0 = blockIdx.x * 128;   // n
    const int j0 = blockIdx.y * 128;   // j
    const int b = blockIdx.z;
    float acc[4][4][4];
    #pragma unroll
    for (int i = 0; i < 4; i++)
        #pragma unroll
        for (int j = 0; j < 4; j++)
            #pragma unroll
            for (int r = 0; r < 4; r++) acc[i][j][r] = 0.f;

    mma_mainloop(smem,
                 g_vhi + ((size_t)b * NN + m0) * 512, g_vlo + ((size_t)b * NN + m0) * 512,
                 g_awhi + ((size_t)b * 512 + j0) * 512, g_awlo + ((size_t)b * 512 + j0) * 512,
                 acc);

    const int tid = threadIdx.x;
    const int wid = tid >> 5, lane = tid & 31;
    const int wm = wid >> 2, wn = wid & 3;
    const int nbase = m0 + wm * 64 + (lane >> 2);
    const int jbase = j0 + wn * 32 + 2 * (lane & 3);
    #pragma unroll
    for (int mi = 0; mi < 4; mi++)
        #pragma unroll
        for (int h = 0; h < 2; h++) {
            int n = nbase + mi * 16 + h * 8;
            float* orow = out + ((size_t)b * NN + n) * DIM + jbase;
            #pragma unroll
            for (int nj = 0; nj < 4; nj++) {
                float2 v = make_float2(acc[mi][nj][h * 2], acc[mi][nj][h * 2 + 1]);
                *(float2*)(orow + nj * 8) = v;
            }
        }
}

// -------- launch --------
extern "C" void kernel_launch(void* const* d_in, const int* in_sizes, int n_in,
                              void* d_out, int out_size) {
    const float* x           = (const float*)d_in[0];
    const float* gamma       = (const float*)d_in[1];
    const float* w_qkv       = (const float*)d_in[2];
    const float* temperature = (const float*)d_in[3];
    const float* w_out       = (const float*)d_in[4];
    float* out = (float*)d_out;

    static int attr_done = 0;
    if (!attr_done) {
        cudaFuncSetAttribute(k_qkv_mma, cudaFuncAttributeMaxDynamicSharedMemorySize, SMEM_BYTES);
        cudaFuncSetAttribute(k_final_mma, cudaFuncAttributeMaxDynamicSharedMemorySize, SMEM_BYTES);
        attr_done = 1;
    }

    k_prepA    <<<BB * NN, 128>>>(x, gamma);
    k_prepW    <<<dim3(48, 16), dim3(32, 8)>>>(w_qkv);
    k_qkv_mma  <<<dim3(256, 12), 256, SMEM_BYTES>>>();
    k_rownorm  <<<2 * BH * DHEAD, 256>>>();
    k_simpart  <<<dim3(BH, 8), 256>>>();
    k_softmax  <<<BH, 64>>>(temperature);
    k_attnw    <<<dim3(BH, 4), 256>>>(w_out);
    k_final_mma<<<dim3(32, 4, BB), 256, SMEM_BYTES>>>(out);
}

// round 5
// speedup vs baseline: 2.8599x; 1.0645x over previous
#include <cuda_runtime.h>
#include <cuda_bf16.h>
#include <math.h>
#include <stdint.h>

#define BB 8
#define NN 4096
#define DIM 512
#define HEADS 8
#define DHEAD 64
#define DINNER 512
#define BH (BB*HEADS)       // 64

// ---------------- scratch (static device globals) ----------------
__device__ __nv_bfloat16 g_qhi[(size_t)BB*DINNER*NN]; // [b][hd][n]
__device__ __nv_bfloat16 g_qlo[(size_t)BB*DINNER*NN];
__device__ __nv_bfloat16 g_khi[(size_t)BB*DINNER*NN];
__device__ __nv_bfloat16 g_klo[(size_t)BB*DINNER*NN];
__device__ __nv_bfloat16 g_vhi[(size_t)BB*NN*DINNER]; // [b][n][c]
__device__ __nv_bfloat16 g_vlo[(size_t)BB*NN*DINNER];
__device__ __nv_bfloat16 g_xhi[(size_t)BB*NN*DIM];    // normalized x, [m][k]
__device__ __nv_bfloat16 g_xlo[(size_t)BB*NN*DIM];
__device__ __nv_bfloat16 g_whi[1536*DIM];             // w_qkv^T, [c][k]
__device__ __nv_bfloat16 g_wlo[1536*DIM];
__device__ __nv_bfloat16 g_awhi[(size_t)BB*DIM*DINNER]; // attn-folded w_out^T, [b][j][c]
__device__ __nv_bfloat16 g_awlo[(size_t)BB*DIM*DINNER];
__device__ float g_invnq[BH*DHEAD];
__device__ float g_invnk[BH*DHEAD];
__device__ float g_gpart[BH*8*DHEAD*DHEAD];
__device__ float g_attn[BH*DHEAD*DHEAD];

// ---------------- helpers ----------------
__device__ __forceinline__ uint32_t smem_u32(const void* p) {
    uint32_t a;
    asm("{ .reg .u64 t; cvta.to.shared.u64 t, %1; cvt.u32.u64 %0, t; }" : "=r"(a) : "l"(p));
    return a;
}
// swizzle for 64B rows (32 bf16): XOR c16 bits with row bits (repeats / 8 rows)
__device__ __forceinline__ uint32_t sw64(uint32_t o) { return o ^ ((o >> 3) & 0x30); }

__device__ __forceinline__ void ldsm4(uint32_t* r, uint32_t addr) {
    asm volatile("ldmatrix.sync.aligned.m8n8.x4.shared.b16 {%0,%1,%2,%3}, [%4];"
                 : "=r"(r[0]), "=r"(r[1]), "=r"(r[2]), "=r"(r[3]) : "r"(addr));
}
__device__ __forceinline__ void mma16816(float* d, const uint32_t* a, const uint32_t* b) {
    asm volatile("mma.sync.aligned.m16n8k16.row.col.f32.bf16.bf16.f32 "
                 "{%0,%1,%2,%3}, {%4,%5,%6,%7}, {%8,%9}, {%0,%1,%2,%3};"
                 : "+f"(d[0]), "+f"(d[1]), "+f"(d[2]), "+f"(d[3])
                 : "r"(a[0]), "r"(a[1]), "r"(a[2]), "r"(a[3]), "r"(b[0]), "r"(b[1]));
}
__device__ __forceinline__ void cpasync16(uint32_t dst, const void* src) {
    asm volatile("cp.async.ca.shared.global [%0], [%1], 16;" :: "r"(dst), "l"(src) : "memory");
}
#define CP_COMMIT() asm volatile("cp.async.commit_group;" ::: "memory")
#define CP_WAIT(n)  asm volatile("cp.async.wait_group %0;" :: "n"(n) : "memory")

__device__ __forceinline__ void split2(float a, float b, uint32_t& hi, uint32_t& lo) {
    __nv_bfloat16 ha = __float2bfloat16(a), hb = __float2bfloat16(b);
    __nv_bfloat16 la = __float2bfloat16(a - __bfloat162float(ha));
    __nv_bfloat16 lb = __float2bfloat16(b - __bfloat162float(hb));
    hi = (uint32_t)*reinterpret_cast<unsigned short*>(&ha) |
         ((uint32_t)*reinterpret_cast<unsigned short*>(&hb) << 16);
    lo = (uint32_t)*reinterpret_cast<unsigned short*>(&la) |
         ((uint32_t)*reinterpret_cast<unsigned short*>(&lb) << 16);
}
__device__ __forceinline__ void split_s(float v, unsigned short& h, unsigned short& l) {
    __nv_bfloat16 bh = __float2bfloat16(v);
    __nv_bfloat16 bl = __float2bfloat16(v - __bfloat162float(bh));
    h = *reinterpret_cast<unsigned short*>(&bh);
    l = *reinterpret_cast<unsigned short*>(&bl);
}

// ======= pipelined split-bf16 MMA mainloop =======
// warp grid 2(m) x 4(n); warp tile (AM*16) x (BN*8); K chunks of 32, double-buffered.
// D += Ahi*Bhi^T + Alo*Bhi^T + Ahi*Blo^T  (3-term Markidis, ~fp32 precision)
template<int ROWS, int AM, int BN, int NCH>
__device__ __forceinline__ void mma_pipe(char* smem,
        const __nv_bfloat16* __restrict__ Ahi, const __nv_bfloat16* __restrict__ Alo,
        const __nv_bfloat16* __restrict__ Bhi, const __nv_bfloat16* __restrict__ Blo,
        int ldA, int ldB, float (*acc)[BN][4]) {
    const int tid = threadIdx.x;
    const int wid = tid >> 5, lane = tid & 31;
    const int wm = wid >> 2, wn = wid & 3;
    const int g = lane >> 3, lr = lane & 7;
    const uint32_t sb = smem_u32(smem);
    constexpr int TILE = ROWS * 64;        // bytes per tile (32 bf16/row)
    constexpr int STAGE = 4 * TILE;
    constexpr int LIT = (ROWS * 4) / 256;  // 16B-chunks per thread per tile
    constexpr int NB = (BN + 1) / 2;
    const int a_row = wm * (AM * 16) + lr + (g & 1) * 8;
    const int a_cb = (g >> 1);
    const int b_row = wn * (BN * 8) + lr + (g >> 1) * 8;
    const int b_cb = (g & 1);

    auto issue = [&](int ch, int st) {
        uint32_t base = sb + st * STAGE;
        #pragma unroll
        for (int i = 0; i < LIT; i++) {
            int idx = tid + 256 * i;
            int row = idx >> 2, c = idx & 3;
            uint32_t so = sw64((uint32_t)(row * 64 + c * 16));
            int col = ch * 32 + c * 8;
            cpasync16(base + 0 * TILE + so, Ahi + (size_t)row * ldA + col);
            cpasync16(base + 1 * TILE + so, Alo + (size_t)row * ldA + col);
            cpasync16(base + 2 * TILE + so, Bhi + (size_t)row * ldB + col);
            cpasync16(base + 3 * TILE + so, Blo + (size_t)row * ldB + col);
        }
    };

    issue(0, 0);
    CP_COMMIT();
    for (int ch = 0; ch < NCH; ch++) {
        if (ch + 1 < NCH) {
            issue(ch + 1, (ch + 1) & 1);
            CP_COMMIT();
            CP_WAIT(1);
        } else {
            CP_WAIT(0);
        }
        __syncthreads();
        uint32_t stb = sb + (ch & 1) * STAGE;
        #pragma unroll
        for (int ks = 0; ks < 2; ks++) {
            uint32_t ah[AM][4], al[AM][4], bfr[NB][4];
            #pragma unroll
            for (int mi = 0; mi < AM; mi++) {
                uint32_t off = sw64((uint32_t)((a_row + mi * 16) * 64 + (a_cb + ks * 2) * 16));
                ldsm4(ah[mi], stb + 0 * TILE + off);
                ldsm4(al[mi], stb + 1 * TILE + off);
            }
            #pragma unroll
            for (int t = 0; t < NB; t++) {
                uint32_t off = sw64((uint32_t)((b_row + t * 16) * 64 + (b_cb + ks * 2) * 16));
                ldsm4(bfr[t], stb + 2 * TILE + off);
            }
            #pragma unroll
            for (int mi = 0; mi < AM; mi++)
                #pragma unroll
                for (int nj = 0; nj < BN; nj++)
                    mma16816(acc[mi][nj], ah[mi], &bfr[nj >> 1][(nj & 1) * 2]);
            #pragma unroll
            for (int mi = 0; mi < AM; mi++)
                #pragma unroll
                for (int nj = 0; nj < BN; nj++)
                    mma16816(acc[mi][nj], al[mi], &bfr[nj >> 1][(nj & 1) * 2]);
            #pragma unroll
            for (int t = 0; t < NB; t++) {
                uint32_t off = sw64((uint32_t)((b_row + t * 16) * 64 + (b_cb + ks * 2) * 16));
                ldsm4(bfr[t], stb + 3 * TILE + off);
            }
            #pragma unroll
            for (int mi = 0; mi < AM; mi++)
                #pragma unroll
                for (int nj = 0; nj < BN; nj++)
                    mma16816(acc[mi][nj], ah[mi], &bfr[nj >> 1][(nj & 1) * 2]);
        }
        __syncthreads();
    }
}

#define SMEM_GEMM (2 * 4 * 128 * 64)   // 65536
#define SMEM_SIM  (2 * 4 * 64 * 64)    // 32768

// -------- K0a: fused RMSNorm + bf16 hi/lo split of activations ----
__global__ void k_prepA(const float* __restrict__ x, const float* __restrict__ gamma) {
    const int row = blockIdx.x;
    const int tid = threadIdx.x;
    const float4 v = ((const float4*)(x + (size_t)row * DIM))[tid];
    float s = v.x * v.x + v.y * v.y + v.z * v.z + v.w * v.w;
    #pragma unroll
    for (int o = 16; o; o >>= 1) s += __shfl_xor_sync(0xffffffffu, s, o);
    __shared__ float ws[4];
    __shared__ float rs_sh;
    if ((tid & 31) == 0) ws[tid >> 5] = s;
    __syncthreads();
    if (tid == 0)
        rs_sh = 22.62741699796952f / fmaxf(sqrtf(ws[0] + ws[1] + ws[2] + ws[3]), 1e-12f);
    __syncthreads();
    const float rs = rs_sh;
    const float4 g = ((const float4*)gamma)[tid];
    float a0 = v.x * rs * g.x, a1 = v.y * rs * g.y, a2 = v.z * rs * g.z, a3 = v.w * rs * g.w;
    uint2 ph, pl;
    split2(a0, a1, ph.x, pl.x);
    split2(a2, a3, ph.y, pl.y);
    ((uint2*)(g_xhi + (size_t)row * DIM))[tid] = ph;
    ((uint2*)(g_xlo + (size_t)row * DIM))[tid] = pl;
}

// -------- K0b: transpose + split w_qkv -> [c][k] hi/lo --------
__global__ void k_prepW(const float* __restrict__ w) {
    __shared__ float t[32][33];
    const int c0 = blockIdx.x * 32, k0 = blockIdx.y * 32;
    const int tx = threadIdx.x, ty = threadIdx.y;
    #pragma unroll
    for (int i = 0; i < 4; i++)
        t[ty + 8 * i][tx] = w[(size_t)(k0 + ty + 8 * i) * 1536 + c0 + tx];
    __syncthreads();
    #pragma unroll
    for (int i = 0; i < 4; i++) {
        float v = t[tx][ty + 8 * i];
        __nv_bfloat16 h = __float2bfloat16(v);
        __nv_bfloat16 l = __float2bfloat16(v - __bfloat162float(h));
        size_t o = (size_t)(c0 + ty + 8 * i) * 512 + k0 + tx;
        g_whi[o] = h;
        g_wlo[o] = l;
    }
}

// -------- QKV GEMM: D[m][c] = xn @ w_qkv --------
__global__ __launch_bounds__(256, 2) void k_qkv_mma() {
    extern __shared__ char smem[];
    const int m0 = blockIdx.x * 128;
    const int c0 = blockIdx.y * 128;
    float acc[4][4][4];
    #pragma unroll
    for (int i = 0; i < 4; i++)
        #pragma unroll
        for (int j = 0; j < 4; j++)
            #pragma unroll
            for (int r = 0; r < 4; r++) acc[i][j][r] = 0.f;

    mma_pipe<128, 4, 4, 16>(smem,
                 g_xhi + (size_t)m0 * 512, g_xlo + (size_t)m0 * 512,
                 g_whi + (size_t)c0 * 512, g_wlo + (size_t)c0 * 512,
                 512, 512, acc);

    const int tid = threadIdx.x;
    const int wid = tid >> 5, lane = tid & 31;
    const int wm = wid >> 2, wn = wid & 3;
    const int b = m0 >> 12;
    const int nbase = (m0 & 4095) + wm * 64 + (lane >> 2);
    const int cloc = wn * 32 + 2 * (lane & 3);
    const int which = c0 >> 9;          // 0:q 1:k 2:v (tile never straddles)
    const int cbase = (c0 & 511) + cloc;

    if (which < 2) {
        __nv_bfloat16* dhi = (which ? g_khi : g_qhi) + (size_t)b * DINNER * NN;
        __nv_bfloat16* dlo = (which ? g_klo : g_qlo) + (size_t)b * DINNER * NN;
        #pragma unroll
        for (int mi = 0; mi < 4; mi++)
            #pragma unroll
            for (int nj = 0; nj < 4; nj++) {
                int c = cbase + nj * 8;
                #pragma unroll
                for (int h = 0; h < 2; h++) {
                    int n = nbase + mi * 16 + h * 8;
                    unsigned short h0, l0, h1, l1;
                    split_s(acc[mi][nj][h * 2], h0, l0);
                    split_s(acc[mi][nj][h * 2 + 1], h1, l1);
                    *(unsigned short*)(dhi + (size_t)c * NN + n) = h0;
                    *(unsigned short*)(dlo + (size_t)c * NN + n) = l0;
                    *(unsigned short*)(dhi + (size_t)(c + 1) * NN + n) = h1;
                    *(unsigned short*)(dlo + (size_t)(c + 1) * NN + n) = l1;
                }
            }
    } else {
        #pragma unroll
        for (int mi = 0; mi < 4; mi++)
            #pragma unroll
            for (int h = 0; h < 2; h++) {
                int n = nbase + mi * 16 + h * 8;
                size_t base = ((size_t)b * NN + n) * DINNER + cbase;
                #pragma unroll
                for (int nj = 0; nj < 4; nj++) {
                    uint32_t hi, lo;
                    split2(acc[mi][nj][h * 2], acc[mi][nj][h * 2 + 1], hi, lo);
                    *(uint32_t*)(g_vhi + base + nj * 8) = hi;
                    *(uint32_t*)(g_vlo + base + nj * 8) = lo;
                }
            }
    }
}

// -------- K3: 1/||row|| over n for q and k (from hi+lo) --------
__global__ void k_rownorm() {
    int row = blockIdx.x;              // 0..8191 (q rows then k rows)
    int r = row & 4095;
    const __nv_bfloat16* ph = ((row < 4096) ? g_qhi : g_khi) + (size_t)r * NN;
    const __nv_bfloat16* pl = ((row < 4096) ? g_qlo : g_klo) + (size_t)r * NN;
    int tid = threadIdx.x;
    float s = 0.f;
    #pragma unroll
    for (int t = 0; t < 2; t++) {
        int idx = (tid + 256 * t) * 8;
        uint4 vh = *(const uint4*)(ph + idx);
        uint4 vl = *(const uint4*)(pl + idx);
        const uint32_t* hw = &vh.x;
        const uint32_t* lw = &vl.x;
        #pragma unroll
        for (int i = 0; i < 4; i++) {
            float2 h2 = __bfloat1622float2(*(const __nv_bfloat162*)&hw[i]);
            float2 l2 = __bfloat1622float2(*(const __nv_bfloat162*)&lw[i]);
            float v0 = h2.x + l2.x, v1 = h2.y + l2.y;
            s += v0 * v0 + v1 * v1;
        }
    }
    #pragma unroll
    for (int o = 16; o; o >>= 1) s += __shfl_xor_sync(0xffffffffu, s, o);
    __shared__ float ws[8];
    if ((tid & 31) == 0) ws[tid >> 5] = s;
    __syncthreads();
    if (tid == 0) {
        float t = 0.f;
        #pragma unroll
        for (int i = 0; i < 8; i++) t += ws[i];
        float inv = 1.0f / fmaxf(sqrtf(t), 1e-12f);
        if (row < 4096) g_invnq[row] = inv; else g_invnk[row & 4095] = inv;
    }
}

// -------- K4: sim partials via HMMA: G[bh][d][e] over a 512-wide n slice ----
__global__ __launch_bounds__(256) void k_sim_mma() {
    extern __shared__ char smem[];
    const int bh = blockIdx.x;   // 64
    const int sp = blockIdx.y;   // 8 splits of n
    float acc[2][2][4];
    #pragma unroll
    for (int i = 0; i < 2; i++)
        #pragma unroll
        for (int j = 0; j < 2; j++)
            #pragma unroll
            for (int r = 0; r < 4; r++) acc[i][j][r] = 0.f;

    const size_t base = (size_t)bh * DHEAD * NN + sp * 512;
    mma_pipe<64, 2, 2, 16>(smem, g_qhi + base, g_qlo + base,
                           g_khi + base, g_klo + base, NN, NN, acc);

    const int tid = threadIdx.x;
    const int wid = tid >> 5, lane = tid & 31;
    const int wm = wid >> 2, wn = wid & 3;
    float* gp = g_gpart + ((size_t)bh * 8 + sp) * 4096;
    #pragma unroll
    for (int mi = 0; mi < 2; mi++)
        #pragma unroll
        for (int h = 0; h < 2; h++) {
            int d = wm * 32 + mi * 16 + (lane >> 2) + h * 8;
            #pragma unroll
            for (int nj = 0; nj < 2; nj++) {
                int e = wn * 16 + nj * 8 + 2 * (lane & 3);
                *(float2*)(gp + d * 64 + e) =
                    make_float2(acc[mi][nj][h * 2], acc[mi][nj][h * 2 + 1]);
            }
        }
}

// -------- K5: reduce + scale + softmax --------
__global__ void k_softmax(const float* __restrict__ temperature) {
    const int bh = blockIdx.x;
    const int d = threadIdx.x;
    const int hh = bh & 7;
    const float sc = 8.0f * expf(temperature[hh]) * g_invnq[bh * 64 + d];
    const float* gp = g_gpart + (size_t)bh * 8 * 4096;
    float vals[64];
    float mx = -1e30f;
    #pragma unroll 4
    for (int e = 0; e < 64; e++) {
        float s = 0.f;
        #pragma unroll
        for (int sp = 0; sp < 8; sp++) s += gp[sp * 4096 + d * 64 + e];
        s *= sc * g_invnk[bh * 64 + e];
        vals[e] = s;
        mx = fmaxf(mx, s);
    }
    float sum = 0.f;
    #pragma unroll 4
    for (int e = 0; e < 64; e++) { vals[e] = expf(vals[e] - mx); sum += vals[e]; }
    const float inv = 1.0f / sum;
    #pragma unroll 4
    for (int e = 0; e < 64; e++)
        g_attn[(size_t)bh * 4096 + d * 64 + e] = vals[e] * inv;
}

// -------- K6: fold attn into w_out, write transposed hi/lo [b][j][c] --------
__global__ __launch_bounds__(256) void k_attnw(const float* __restrict__ w_out) {
    const int bh = blockIdx.x;
    const int jt = blockIdx.y;
    const int b = bh >> 3, hh = bh & 7;
    __shared__ float As[64][64];
    const int tid = threadIdx.x;
    #pragma unroll
    for (int t = 0; t < 16; t++) {
        int idx = tid + 256 * t;
        As[idx >> 6][idx & 63] = g_attn[(size_t)bh * 4096 + idx];
    }
    __syncthreads();
    const int j = jt * 128 + (tid & 127);
    const int e0 = (tid >> 7) * 32;
    float acc[32];
    #pragma unroll
    for (int i = 0; i < 32; i++) acc[i] = 0.f;
    for (int d = 0; d < 64; d++) {
        float w = w_out[(hh * 64 + d) * DIM + j];
        #pragma unroll
        for (int i = 0; i < 32; i++) acc[i] += As[d][e0 + i] * w;
    }
    size_t base = ((size_t)b * 512 + j) * 512 + hh * 64 + e0;
    #pragma unroll
    for (int i = 0; i < 32; i++) {
        __nv_bfloat16 h = __float2bfloat16(acc[i]);
        __nv_bfloat16 l = __float2bfloat16(acc[i] - __bfloat162float(h));
        g_awhi[base + i] = h;
        g_awlo[base + i] = l;
    }
}

// -------- final GEMM: out[b][n][j] = sum_c V[b][n][c] * aw[b][j][c] --------
__global__ __launch_bounds__(256, 2) void k_final_mma(float* __restrict__ out) {
    extern __shared__ char smem[];
    const int m0 = blockIdx.x * 128;   // n
    const int j0 = blockIdx.y * 128;   // j
    const int b = blockIdx.z;
    float acc[4][4][4];
    #pragma unroll
    for (int i = 0; i < 4; i++)
        #pragma unroll
        for (int j = 0; j < 4; j++)
            #pragma unroll
            for (int r = 0; r < 4; r++) acc[i][j][r] = 0.f;

    mma_pipe<128, 4, 4, 16>(smem,
                 g_vhi + ((size_t)b * NN + m0) * 512, g_vlo + ((size_t)b * NN + m0) * 512,
                 g_awhi + ((size_t)b * 512 + j0) * 512, g_awlo + ((size_t)b * 512 + j0) * 512,
                 512, 512, acc);

    const int tid = threadIdx.x;
    const int wid = tid >> 5, lane = tid & 31;
    const int wm = wid >> 2, wn = wid & 3;
    const int nbase = m0 + wm * 64 + (lane >> 2);
    const int jbase = j0 + wn * 32 + 2 * (lane & 3);
    #pragma unroll
    for (int mi = 0; mi < 4; mi++)
        #pragma unroll
        for (int h = 0; h < 2; h++) {
            int n = nbase + mi * 16 + h * 8;
            float* orow = out + ((size_t)b * NN + n) * DIM + jbase;
            #pragma unroll
            for (int nj = 0; nj < 4; nj++) {
                float2 v = make_float2(acc[mi][nj][h * 2], acc[mi][nj][h * 2 + 1]);
                *(float2*)(orow + nj * 8) = v;
            }
        }
}

// -------- launch --------
extern "C" void kernel_launch(void* const* d_in, const int* in_sizes, int n_in,
                              void* d_out, int out_size) {
    const float* x           = (const float*)d_in[0];
    const float* gamma       = (const float*)d_in[1];
    const float* w_qkv       = (const float*)d_in[2];
    const float* temperature = (const float*)d_in[3];
    const float* w_out       = (const float*)d_in[4];
    float* out = (float*)d_out;

    static int attr_done = 0;
    if (!attr_done) {
        cudaFuncSetAttribute(k_qkv_mma, cudaFuncAttributeMaxDynamicSharedMemorySize, SMEM_GEMM);
        cudaFuncSetAttribute(k_final_mma, cudaFuncAttributeMaxDynamicSharedMemorySize, SMEM_GEMM);
        attr_done = 1;
    }

    k_prepA    <<<BB * NN, 128>>>(x, gamma);
    k_prepW    <<<dim3(48, 16), dim3(32, 8)>>>(w_qkv);
    k_qkv_mma  <<<dim3(256, 12), 256, SMEM_GEMM>>>();
    k_rownorm  <<<2 * BH * DHEAD, 256>>>();
    k_sim_mma  <<<dim3(BH, 8), 256, SMEM_SIM>>>();
    k_softmax  <<<BH, 64>>>(temperature);
    k_attnw    <<<dim3(BH, 4), 256>>>(w_out);
    k_final_mma<<<dim3(32, 4, BB), 256, SMEM_GEMM>>>(out);
}

// round 7
// speedup vs baseline: 3.0350x; 1.0612x over previous
#include <cuda_runtime.h>
#include <cuda_bf16.h>
#include <math.h>
#include <stdint.h>

#define BB 8
#define NN 4096
#define DIM 512
#define HEADS 8
#define DHEAD 64
#define DINNER 512
#define BH (BB*HEADS)       // 64

// ---------------- scratch (static device globals) ----------------
__device__ __nv_bfloat16 g_qhi[(size_t)BB*DINNER*NN]; // [b][hd][n]
__device__ __nv_bfloat16 g_qlo[(size_t)BB*DINNER*NN];
__device__ __nv_bfloat16 g_khi[(size_t)BB*DINNER*NN];
__device__ __nv_bfloat16 g_klo[(size_t)BB*DINNER*NN];
__device__ __nv_bfloat16 g_vhi[(size_t)BB*NN*DINNER]; // [b][n][c]
__device__ __nv_bfloat16 g_vlo[(size_t)BB*NN*DINNER];
__device__ __nv_bfloat16 g_xhi[(size_t)BB*NN*DIM];    // normalized x, [m][k]
__device__ __nv_bfloat16 g_xlo[(size_t)BB*NN*DIM];
__device__ __nv_bfloat16 g_whi[1536*DIM];             // w_qkv^T, [c][k]
__device__ __nv_bfloat16 g_wlo[1536*DIM];
__device__ __nv_bfloat16 g_awhi[(size_t)BB*DIM*DINNER]; // attn-folded w_out^T, [b][j][c]
__device__ __nv_bfloat16 g_awlo[(size_t)BB*DIM*DINNER];
__device__ float g_invnq[BH*DHEAD];
__device__ float g_invnk[BH*DHEAD];
__device__ float g_gpart[BH*8*DHEAD*DHEAD];
__device__ float g_attn[BH*DHEAD*DHEAD];

// ---------------- helpers ----------------
__device__ __forceinline__ uint32_t smem_u32(const void* p) {
    uint32_t a;
    asm("{ .reg .u64 t; cvta.to.shared.u64 t, %1; cvt.u32.u64 %0, t; }" : "=r"(a) : "l"(p));
    return a;
}
// swizzle for 64B rows (32 bf16)
__device__ __forceinline__ uint32_t sw64(uint32_t o) { return o ^ ((o >> 3) & 0x30); }

__device__ __forceinline__ void ldsm4(uint32_t* r, uint32_t addr) {
    asm volatile("ldmatrix.sync.aligned.m8n8.x4.shared.b16 {%0,%1,%2,%3}, [%4];"
                 : "=r"(r[0]), "=r"(r[1]), "=r"(r[2]), "=r"(r[3]) : "r"(addr));
}
__device__ __forceinline__ void mma16816(float* d, const uint32_t* a, const uint32_t* b) {
    asm volatile("mma.sync.aligned.m16n8k16.row.col.f32.bf16.bf16.f32 "
                 "{%0,%1,%2,%3}, {%4,%5,%6,%7}, {%8,%9}, {%0,%1,%2,%3};"
                 : "+f"(d[0]), "+f"(d[1]), "+f"(d[2]), "+f"(d[3])
                 : "r"(a[0]), "r"(a[1]), "r"(a[2]), "r"(a[3]), "r"(b[0]), "r"(b[1]));
}
__device__ __forceinline__ void cpasync16(uint32_t dst, const void* src) {
    asm volatile("cp.async.cg.shared.global [%0], [%1], 16;" :: "r"(dst), "l"(src) : "memory");
}
#define CP_COMMIT() asm volatile("cp.async.commit_group;" ::: "memory")
#define CP_WAIT1()  asm volatile("cp.async.wait_group 1;" ::: "memory")
#define CP_WAIT0()  asm volatile("cp.async.wait_group 0;" ::: "memory")

__device__ __forceinline__ void split2(float a, float b, uint32_t& hi, uint32_t& lo) {
    __nv_bfloat16 ha = __float2bfloat16(a), hb = __float2bfloat16(b);
    __nv_bfloat16 la = __float2bfloat16(a - __bfloat162float(ha));
    __nv_bfloat16 lb = __float2bfloat16(b - __bfloat162float(hb));
    hi = (uint32_t)*reinterpret_cast<unsigned short*>(&ha) |
         ((uint32_t)*reinterpret_cast<unsigned short*>(&hb) << 16);
    lo = (uint32_t)*reinterpret_cast<unsigned short*>(&la) |
         ((uint32_t)*reinterpret_cast<unsigned short*>(&lb) << 16);
}
__device__ __forceinline__ void split_s(float v, unsigned short& h, unsigned short& l) {
    __nv_bfloat16 bh = __float2bfloat16(v);
    __nv_bfloat16 bl = __float2bfloat16(v - __bfloat162float(bh));
    h = *reinterpret_cast<unsigned short*>(&bh);
    l = *reinterpret_cast<unsigned short*>(&bl);
}

// ======= 3-stage pipelined split-bf16 MMA mainloop =======
// warp grid 2(m) x 4(n); warp tile (AM*16) x (BN*8); K chunks of 32.
// D += Ahi*Bhi^T + Alo*Bhi^T + Ahi*Blo^T  (3-term Markidis, ~fp32 precision)
// One __syncthreads per chunk: issuing stage (ch+2)%3 overwrites stage
// (ch-1)%3, fully consumed before this iteration's barrier.
template<int ROWS, int AM, int BN, int NCH>
__device__ __forceinline__ void mma_pipe(char* smem,
        const __nv_bfloat16* __restrict__ Ahi, const __nv_bfloat16* __restrict__ Alo,
        const __nv_bfloat16* __restrict__ Bhi, const __nv_bfloat16* __restrict__ Blo,
        int ldA, int ldB, float (*acc)[BN][4]) {
    const int tid = threadIdx.x;
    const int wid = tid >> 5, lane = tid & 31;
    const int wm = wid >> 2, wn = wid & 3;
    const int g = lane >> 3, lr = lane & 7;
    const uint32_t sb = smem_u32(smem);
    constexpr int TILE = ROWS * 64;        // bytes per tile (32 bf16/row)
    constexpr int STAGE = 4 * TILE;
    constexpr int LIT = (ROWS * 4) / 256;  // 16B-chunks per thread per tile
    constexpr int NB = (BN + 1) / 2;
    const int a_row = wm * (AM * 16) + lr + (g & 1) * 8;
    const int a_cb = (g >> 1);
    const int b_row = wn * (BN * 8) + lr + (g >> 1) * 8;
    const int b_cb = (g & 1);

    auto issue = [&](int ch, int st) {
        uint32_t base = sb + st * STAGE;
        #pragma unroll
        for (int i = 0; i < LIT; i++) {
            int idx = tid + 256 * i;
            int row = idx >> 2, c = idx & 3;
            uint32_t so = sw64((uint32_t)(row * 64 + c * 16));
            int col = ch * 32 + c * 8;
            cpasync16(base + 0 * TILE + so, Ahi + (size_t)row * ldA + col);
            cpasync16(base + 1 * TILE + so, Alo + (size_t)row * ldA + col);
            cpasync16(base + 2 * TILE + so, Bhi + (size_t)row * ldB + col);
            cpasync16(base + 3 * TILE + so, Blo + (size_t)row * ldB + col);
        }
    };

    issue(0, 0); CP_COMMIT();
    issue(1, 1); CP_COMMIT();
    for (int ch = 0; ch < NCH; ch++) {
        if (ch < NCH - 1) { CP_WAIT1(); } else { CP_WAIT0(); }
        __syncthreads();
        if (ch + 2 < NCH) { issue(ch + 2, (ch + 2) % 3); CP_COMMIT(); }
        uint32_t stb = sb + (ch % 3) * STAGE;
        #pragma unroll
        for (int ks = 0; ks < 2; ks++) {
            uint32_t ah[AM][4], al[AM][4], bfr[NB][4];
            #pragma unroll
            for (int mi = 0; mi < AM; mi++) {
                uint32_t off = sw64((uint32_t)((a_row + mi * 16) * 64 + (a_cb + ks * 2) * 16));
                ldsm4(ah[mi], stb + 0 * TILE + off);
                ldsm4(al[mi], stb + 1 * TILE + off);
            }
            #pragma unroll
            for (int t = 0; t < NB; t++) {
                uint32_t off = sw64((uint32_t)((b_row + t * 16) * 64 + (b_cb + ks * 2) * 16));
                ldsm4(bfr[t], stb + 2 * TILE + off);
            }
            #pragma unroll
            for (int mi = 0; mi < AM; mi++)
                #pragma unroll
                for (int nj = 0; nj < BN; nj++)
                    mma16816(acc[mi][nj], ah[mi], &bfr[nj >> 1][(nj & 1) * 2]);
            #pragma unroll
            for (int mi = 0; mi < AM; mi++)
                #pragma unroll
                for (int nj = 0; nj < BN; nj++)
                    mma16816(acc[mi][nj], al[mi], &bfr[nj >> 1][(nj & 1) * 2]);
            #pragma unroll
            for (int t = 0; t < NB; t++) {
                uint32_t off = sw64((uint32_t)((b_row + t * 16) * 64 + (b_cb + ks * 2) * 16));
                ldsm4(bfr[t], stb + 3 * TILE + off);
            }
            #pragma unroll
            for (int mi = 0; mi < AM; mi++)
                #pragma unroll
                for (int nj = 0; nj < BN; nj++)
                    mma16816(acc[mi][nj], ah[mi], &bfr[nj >> 1][(nj & 1) * 2]);
        }
    }
    __syncthreads();
}

#define SMEM_GEMM (3 * 4 * 128 * 64)   // 98304
#define SMEM_SIM  (3 * 4 * 64 * 64)    // 49152

// -------- K0a: fused RMSNorm + bf16 hi/lo split of activations ----
__global__ void k_prepA(const float* __restrict__ x, const float* __restrict__ gamma) {
    const int row = blockIdx.x;
    const int tid = threadIdx.x;
    const float4 v = ((const float4*)(x + (size_t)row * DIM))[tid];
    float s = v.x * v.x + v.y * v.y + v.z * v.z + v.w * v.w;
    #pragma unroll
    for (int o = 16; o; o >>= 1) s += __shfl_xor_sync(0xffffffffu, s, o);
    __shared__ float ws[4];
    __shared__ float rs_sh;
    if ((tid & 31) == 0) ws[tid >> 5] = s;
    __syncthreads();
    if (tid == 0)
        rs_sh = 22.62741699796952f / fmaxf(sqrtf(ws[0] + ws[1] + ws[2] + ws[3]), 1e-12f);
    __syncthreads();
    const float rs = rs_sh;
    const float4 g = ((const float4*)gamma)[tid];
    float a0 = v.x * rs * g.x, a1 = v.y * rs * g.y, a2 = v.z * rs * g.z, a3 = v.w * rs * g.w;
    uint2 ph, pl;
    split2(a0, a1, ph.x, pl.x);
    split2(a2, a3, ph.y, pl.y);
    ((uint2*)(g_xhi + (size_t)row * DIM))[tid] = ph;
    ((uint2*)(g_xlo + (size_t)row * DIM))[tid] = pl;
}

// -------- K0b: transpose + split w_qkv -> [c][k] hi/lo --------
__global__ void k_prepW(const float* __restrict__ w) {
    __shared__ float t[32][33];
    const int c0 = blockIdx.x * 32, k0 = blockIdx.y * 32;
    const int tx = threadIdx.x, ty = threadIdx.y;
    #pragma unroll
    for (int i = 0; i < 4; i++)
        t[ty + 8 * i][tx] = w[(size_t)(k0 + ty + 8 * i) * 1536 + c0 + tx];
    __syncthreads();
    #pragma unroll
    for (int i = 0; i < 4; i++) {
        float v = t[tx][ty + 8 * i];
        __nv_bfloat16 h = __float2bfloat16(v);
        __nv_bfloat16 l = __float2bfloat16(v - __bfloat162float(h));
        size_t o = (size_t)(c0 + ty + 8 * i) * 512 + k0 + tx;
        g_whi[o] = h;
        g_wlo[o] = l;
    }
}

// -------- QKV GEMM: D[m][c] = xn @ w_qkv --------
__global__ __launch_bounds__(256, 2) void k_qkv_mma() {
    extern __shared__ char smem[];
    const int m0 = blockIdx.x * 128;
    const int c0 = blockIdx.y * 128;
    float acc[4][4][4];
    #pragma unroll
    for (int i = 0; i < 4; i++)
        #pragma unroll
        for (int j = 0; j < 4; j++)
            #pragma unroll
            for (int r = 0; r < 4; r++) acc[i][j][r] = 0.f;

    mma_pipe<128, 4, 4, 16>(smem,
                 g_xhi + (size_t)m0 * 512, g_xlo + (size_t)m0 * 512,
                 g_whi + (size_t)c0 * 512, g_wlo + (size_t)c0 * 512,
                 512, 512, acc);

    const int tid = threadIdx.x;
    const int wid = tid >> 5, lane = tid & 31;
    const int wm = wid >> 2, wn = wid & 3;
    const int b = m0 >> 12;
    const int nbase = (m0 & 4095) + wm * 64 + (lane >> 2);
    const int cloc = wn * 32 + 2 * (lane & 3);
    const int which = c0 >> 9;          // 0:q 1:k 2:v (tile never straddles)
    const int cbase = (c0 & 511) + cloc;

    if (which < 2) {
        __nv_bfloat16* dhi = (which ? g_khi : g_qhi) + (size_t)b * DINNER * NN;
        __nv_bfloat16* dlo = (which ? g_klo : g_qlo) + (size_t)b * DINNER * NN;
        #pragma unroll
        for (int mi = 0; mi < 4; mi++)
            #pragma unroll
            for (int nj = 0; nj < 4; nj++) {
                int c = cbase + nj * 8;
                #pragma unroll
                for (int h = 0; h < 2; h++) {
                    int n = nbase + mi * 16 + h * 8;
                    unsigned short h0, l0, h1, l1;
                    split_s(acc[mi][nj][h * 2], h0, l0);
                    split_s(acc[mi][nj][h * 2 + 1], h1, l1);
                    *(unsigned short*)(dhi + (size_t)c * NN + n) = h0;
                    *(unsigned short*)(dlo + (size_t)c * NN + n) = l0;
                    *(unsigned short*)(dhi + (size_t)(c + 1) * NN + n) = h1;
                    *(unsigned short*)(dlo + (size_t)(c + 1) * NN + n) = l1;
                }
            }
    } else {
        #pragma unroll
        for (int mi = 0; mi < 4; mi++)
            #pragma unroll
            for (int h = 0; h < 2; h++) {
                int n = nbase + mi * 16 + h * 8;
                size_t base = ((size_t)b * NN + n) * DINNER + cbase;
                #pragma unroll
                for (int nj = 0; nj < 4; nj++) {
                    uint32_t hi, lo;
                    split2(acc[mi][nj][h * 2], acc[mi][nj][h * 2 + 1], hi, lo);
                    *(uint32_t*)(g_vhi + base + nj * 8) = hi;
                    *(uint32_t*)(g_vlo + base + nj * 8) = lo;
                }
            }
    }
}

// -------- K3: 1/||row|| over n for q and k (from hi+lo) --------
__global__ void k_rownorm() {
    int row = blockIdx.x;              // 0..8191 (q rows then k rows)
    int r = row & 4095;
    const __nv_bfloat16* ph = ((row < 4096) ? g_qhi : g_khi) + (size_t)r * NN;
    const __nv_bfloat16* pl = ((row < 4096) ? g_qlo : g_klo) + (size_t)r * NN;
    int tid = threadIdx.x;
    float s = 0.f;
    #pragma unroll
    for (int t = 0; t < 2; t++) {
        int idx = (tid + 256 * t) * 8;
        uint4 vh = *(const uint4*)(ph + idx);
        uint4 vl = *(const uint4*)(pl + idx);
        const uint32_t* hw = &vh.x;
        const uint32_t* lw = &vl.x;
        #pragma unroll
        for (int i = 0; i < 4; i++) {
            float2 h2 = __bfloat1622float2(*(const __nv_bfloat162*)&hw[i]);
            float2 l2 = __bfloat1622float2(*(const __nv_bfloat162*)&lw[i]);
            float v0 = h2.x + l2.x, v1 = h2.y + l2.y;
            s += v0 * v0 + v1 * v1;
        }
    }
    #pragma unroll
    for (int o = 16; o; o >>= 1) s += __shfl_xor_sync(0xffffffffu, s, o);
    __shared__ float ws[8];
    if ((tid & 31) == 0) ws[tid >> 5] = s;
    __syncthreads();
    if (tid == 0) {
        float t = 0.f;
        #pragma unroll
        for (int i = 0; i < 8; i++) t += ws[i];
        float inv = 1.0f / fmaxf(sqrtf(t), 1e-12f);
        if (row < 4096) g_invnq[row] = inv; else g_invnk[row & 4095] = inv;
    }
}

// -------- K4: sim partials via HMMA: G[bh][d][e] over a 512-wide n slice ----
__global__ __launch_bounds__(256) void k_sim_mma() {
    extern __shared__ char smem[];
    const int bh = blockIdx.x;   // 64
    const int sp = blockIdx.y;   // 8 splits of n
    float acc[2][2][4];
    #pragma unroll
    for (int i = 0; i < 2; i++)
        #pragma unroll
        for (int j = 0; j < 2; j++)
            #pragma unroll
            for (int r = 0; r < 4; r++) acc[i][j][r] = 0.f;

    const size_t base = (size_t)bh * DHEAD * NN + sp * 512;
    mma_pipe<64, 2, 2, 16>(smem, g_qhi + base, g_qlo + base,
                           g_khi + base, g_klo + base, NN, NN, acc);

    const int tid = threadIdx.x;
    const int wid = tid >> 5, lane = tid & 31;
    const int wm = wid >> 2, wn = wid & 3;
    float* gp = g_gpart + ((size_t)bh * 8 + sp) * 4096;
    #pragma unroll
    for (int mi = 0; mi < 2; mi++)
        #pragma unroll
        for (int h = 0; h < 2; h++) {
            int d = wm * 32 + mi * 16 + (lane >> 2) + h * 8;
            #pragma unroll
            for (int nj = 0; nj < 2; nj++) {
                int e = wn * 16 + nj * 8 + 2 * (lane & 3);
                *(float2*)(gp + d * 64 + e) =
                    make_float2(acc[mi][nj][h * 2], acc[mi][nj][h * 2 + 1]);
            }
        }
}

// -------- K5: reduce + scale + softmax --------
__global__ void k_softmax(const float* __restrict__ temperature) {
    const int bh = blockIdx.x;
    const int d = threadIdx.x;
    const int hh = bh & 7;
    const float sc = 8.0f * expf(temperature[hh]) * g_invnq[bh * 64 + d];
    const float* gp = g_gpart + (size_t)bh * 8 * 4096;
    float vals[64];
    float mx = -1e30f;
    #pragma unroll 4
    for (int e = 0; e < 64; e++) {
        float s = 0.f;
        #pragma unroll
        for (int sp = 0; sp < 8; sp++) s += gp[sp * 4096 + d * 64 + e];
        s *= sc * g_invnk[bh * 64 + e];
        vals[e] = s;
        mx = fmaxf(mx, s);
    }
    float sum = 0.f;
    #pragma unroll 4
    for (int e = 0; e < 64; e++) { vals[e] = expf(vals[e] - mx); sum += vals[e]; }
    const float inv = 1.0f / sum;
    #pragma unroll 4
    for (int e = 0; e < 64; e++)
        g_attn[(size_t)bh * 4096 + d * 64 + e] = vals[e] * inv;
}

// -------- K6: fold attn into w_out, write transposed hi/lo [b][j][c] --------
__global__ __launch_bounds__(256) void k_attnw(const float* __restrict__ w_out) {
    const int bh = blockIdx.x;
    const int jt = blockIdx.y;
    const int b = bh >> 3, hh = bh & 7;
    __shared__ float As[64][64];
    const int tid = threadIdx.x;
    #pragma unroll
    for (int t = 0; t < 16; t++) {
        int idx = tid + 256 * t;
        As[idx >> 6][idx & 63] = g_attn[(size_t)bh * 4096 + idx];
    }
    __syncthreads();
    const int j = jt * 128 + (tid & 127);
    const int e0 = (tid >> 7) * 32;
    float acc[32];
    #pragma unroll
    for (int i = 0; i < 32; i++) acc[i] = 0.f;
    for (int d = 0; d < 64; d++) {
        float w = w_out[(hh * 64 + d) * DIM + j];
        #pragma unroll
        for (int i = 0; i < 32; i++) acc[i] += As[d][e0 + i] * w;
    }
    size_t base = ((size_t)b * 512 + j) * 512 + hh * 64 + e0;
    #pragma unroll
    for (int i = 0; i < 32; i++) {
        __nv_bfloat16 h = __float2bfloat16(acc[i]);
        __nv_bfloat16 l = __float2bfloat16(acc[i] - __bfloat162float(h));
        g_awhi[base + i] = h;
        g_awlo[base + i] = l;
    }
}

// -------- final GEMM: out[b][n][j] = sum_c V[b][n][c] * aw[b][j][c] --------
__global__ __launch_bounds__(256, 2) void k_final_mma(float* __restrict__ out) {
    extern __shared__ char smem[];
    const int m0 = blockIdx.x * 128;   // n
    const int j0 = blockIdx.y * 128;   // j
    const int b = blockIdx.z;
    float acc[4][4][4];
    #pragma unroll
    for (int i = 0; i < 4; i++)
        #pragma unroll
        for (int j = 0; j < 4; j++)
            #pragma unroll
            for (int r = 0; r < 4; r++) acc[i][j][r] = 0.f;

    mma_pipe<128, 4, 4, 16>(smem,
                 g_vhi + ((size_t)b * NN + m0) * 512, g_vlo + ((size_t)b * NN + m0) * 512,
                 g_awhi + ((size_t)b * 512 + j0) * 512, g_awlo + ((size_t)b * 512 + j0) * 512,
                 512, 512, acc);

    const int tid = threadIdx.x;
    const int wid = tid >> 5, lane = tid & 31;
    const int wm = wid >> 2, wn = wid & 3;
    const int nbase = m0 + wm * 64 + (lane >> 2);
    const int jbase = j0 + wn * 32 + 2 * (lane & 3);
    #pragma unroll
    for (int mi = 0; mi < 4; mi++)
        #pragma unroll
        for (int h = 0; h < 2; h++) {
            int n = nbase + mi * 16 + h * 8;
            float* orow = out + ((size_t)b * NN + n) * DIM + jbase;
            #pragma unroll
            for (int nj = 0; nj < 4; nj++) {
                float2 v = make_float2(acc[mi][nj][h * 2], acc[mi][nj][h * 2 + 1]);
                *(float2*)(orow + nj * 8) = v;
            }
        }
}

// -------- launch --------
extern "C" void kernel_launch(void* const* d_in, const int* in_sizes, int n_in,
                              void* d_out, int out_size) {
    const float* x           = (const float*)d_in[0];
    const float* gamma       = (const float*)d_in[1];
    const float* w_qkv       = (const float*)d_in[2];
    const float* temperature = (const float*)d_in[3];
    const float* w_out       = (const float*)d_in[4];
    float* out = (float*)d_out;

    static int attr_done = 0;
    if (!attr_done) {
        cudaFuncSetAttribute(k_qkv_mma, cudaFuncAttributeMaxDynamicSharedMemorySize, SMEM_GEMM);
        cudaFuncSetAttribute(k_final_mma, cudaFuncAttributeMaxDynamicSharedMemorySize, SMEM_GEMM);
        cudaFuncSetAttribute(k_sim_mma, cudaFuncAttributeMaxDynamicSharedMemorySize, SMEM_SIM);
        attr_done = 1;
    }

    k_prepA    <<<BB * NN, 128>>>(x, gamma);
    k_prepW    <<<dim3(48, 16), dim3(32, 8)>>>(w_qkv);
    k_qkv_mma  <<<dim3(256, 12), 256, SMEM_GEMM>>>();
    k_rownorm  <<<2 * BH * DHEAD, 256>>>();
    k_sim_mma  <<<dim3(BH, 8), 256, SMEM_SIM>>>();
    k_softmax  <<<BH, 64>>>(temperature);
    k_attnw    <<<dim3(BH, 4), 256>>>(w_out);
    k_final_mma<<<dim3(32, 4, BB), 256, SMEM_GEMM>>>(out);
}

// round 8
// speedup vs baseline: 4.0678x; 1.3403x over previous
#include <cuda_runtime.h>
#include <cuda_fp16.h>
#include <math.h>
#include <stdint.h>

#define BB 8
#define NN 4096
#define DIM 512
#define HEADS 8
#define DHEAD 64
#define DINNER 512
#define BH (BB*HEADS)       // 64

// ---------------- scratch (static device globals) ----------------
// A-side operands keep hi+lo (fp16 split); B-side operands are fp16-rounded.
__device__ __half g_qhi[(size_t)BB*DINNER*NN]; // [b][hd][n]
__device__ __half g_qlo[(size_t)BB*DINNER*NN];
__device__ __half g_khi[(size_t)BB*DINNER*NN]; // hi only (B side of sim)
__device__ __half g_vhi[(size_t)BB*NN*DINNER]; // [b][n][c]
__device__ __half g_vlo[(size_t)BB*NN*DINNER];
__device__ __half g_xhi[(size_t)BB*NN*DIM];    // normalized x, [m][k]
__device__ __half g_xlo[(size_t)BB*NN*DIM];
__device__ __half g_whi[1536*DIM];             // w_qkv^T, [c][k]  (hi only)
__device__ __half g_awhi[(size_t)BB*DIM*DINNER]; // attn-folded w_out^T, [b][j][c]
__device__ float g_invnq[BH*DHEAD];
__device__ float g_invnk[BH*DHEAD];
__device__ float g_gpart[BH*8*DHEAD*DHEAD];
__device__ float g_attn[BH*DHEAD*DHEAD];

// ---------------- helpers ----------------
__device__ __forceinline__ uint32_t smem_u32(const void* p) {
    uint32_t a;
    asm("{ .reg .u64 t; cvta.to.shared.u64 t, %1; cvt.u32.u64 %0, t; }" : "=r"(a) : "l"(p));
    return a;
}
// swizzle for 64B rows (32 fp16)
__device__ __forceinline__ uint32_t sw64(uint32_t o) { return o ^ ((o >> 3) & 0x30); }

__device__ __forceinline__ void ldsm4(uint32_t* r, uint32_t addr) {
    asm volatile("ldmatrix.sync.aligned.m8n8.x4.shared.b16 {%0,%1,%2,%3}, [%4];"
                 : "=r"(r[0]), "=r"(r[1]), "=r"(r[2]), "=r"(r[3]) : "r"(addr));
}
__device__ __forceinline__ void mma16816(float* d, const uint32_t* a, const uint32_t* b) {
    asm volatile("mma.sync.aligned.m16n8k16.row.col.f32.f16.f16.f32 "
                 "{%0,%1,%2,%3}, {%4,%5,%6,%7}, {%8,%9}, {%0,%1,%2,%3};"
                 : "+f"(d[0]), "+f"(d[1]), "+f"(d[2]), "+f"(d[3])
                 : "r"(a[0]), "r"(a[1]), "r"(a[2]), "r"(a[3]), "r"(b[0]), "r"(b[1]));
}
__device__ __forceinline__ void cpasync16(uint32_t dst, const void* src) {
    asm volatile("cp.async.cg.shared.global [%0], [%1], 16;" :: "r"(dst), "l"(src) : "memory");
}
#define CP_COMMIT() asm volatile("cp.async.commit_group;" ::: "memory")
#define CP_WAIT1()  asm volatile("cp.async.wait_group 1;" ::: "memory")
#define CP_WAIT0()  asm volatile("cp.async.wait_group 0;" ::: "memory")

__device__ __forceinline__ void splith_s(float v, unsigned short& h, unsigned short& l) {
    __half hh = __float2half_rn(v);
    __half ll = __float2half_rn(v - __half2float(hh));
    h = *reinterpret_cast<unsigned short*>(&hh);
    l = *reinterpret_cast<unsigned short*>(&ll);
}
__device__ __forceinline__ void splith2(float a, float b, uint32_t& hi, uint32_t& lo) {
    unsigned short h0, l0, h1, l1;
    splith_s(a, h0, l0);
    splith_s(b, h1, l1);
    hi = (uint32_t)h0 | ((uint32_t)h1 << 16);
    lo = (uint32_t)l0 | ((uint32_t)l1 << 16);
}
__device__ __forceinline__ uint32_t packh2(float a, float b) {
    __half2 h = __floats2half2_rn(a, b);
    return *reinterpret_cast<uint32_t*>(&h);
}

// ======= 3-stage pipelined 2-term fp16 MMA mainloop =======
// warp grid 2(m) x 4(n); warp tile (AM*16) x (BN*8); K chunks of 32.
// D += Ahi*Bhi^T + Alo*Bhi^T   (A fp16-split, B fp16-rounded; err ~2^-12)
template<int ROWS, int AM, int BN, int NCH>
__device__ __forceinline__ void mma_pipe(char* smem,
        const __half* __restrict__ Ahi, const __half* __restrict__ Alo,
        const __half* __restrict__ Bhi,
        int ldA, int ldB, float (*acc)[BN][4]) {
    const int tid = threadIdx.x;
    const int wid = tid >> 5, lane = tid & 31;
    const int wm = wid >> 2, wn = wid & 3;
    const int g = lane >> 3, lr = lane & 7;
    const uint32_t sb = smem_u32(smem);
    constexpr int TILE = ROWS * 64;        // bytes per tile (32 fp16/row)
    constexpr int STAGE = 3 * TILE;
    constexpr int LIT = (ROWS * 4) / 256;  // 16B-chunks per thread per tile
    constexpr int NB = (BN + 1) / 2;
    const int a_row = wm * (AM * 16) + lr + (g & 1) * 8;
    const int a_cb = (g >> 1);
    const int b_row = wn * (BN * 8) + lr + (g >> 1) * 8;
    const int b_cb = (g & 1);

    auto issue = [&](int ch, int st) {
        uint32_t base = sb + st * STAGE;
        #pragma unroll
        for (int i = 0; i < LIT; i++) {
            int idx = tid + 256 * i;
            int row = idx >> 2, c = idx & 3;
            uint32_t so = sw64((uint32_t)(row * 64 + c * 16));
            int col = ch * 32 + c * 8;
            cpasync16(base + 0 * TILE + so, Ahi + (size_t)row * ldA + col);
            cpasync16(base + 1 * TILE + so, Alo + (size_t)row * ldA + col);
            cpasync16(base + 2 * TILE + so, Bhi + (size_t)row * ldB + col);
        }
    };

    issue(0, 0); CP_COMMIT();
    issue(1, 1); CP_COMMIT();
    for (int ch = 0; ch < NCH; ch++) {
        if (ch < NCH - 1) { CP_WAIT1(); } else { CP_WAIT0(); }
        __syncthreads();
        if (ch + 2 < NCH) { issue(ch + 2, (ch + 2) % 3); CP_COMMIT(); }
        uint32_t stb = sb + (ch % 3) * STAGE;
        #pragma unroll
        for (int ks = 0; ks < 2; ks++) {
            uint32_t ah[AM][4], al[AM][4], bfr[NB][4];
            #pragma unroll
            for (int mi = 0; mi < AM; mi++) {
                uint32_t off = sw64((uint32_t)((a_row + mi * 16) * 64 + (a_cb + ks * 2) * 16));
                ldsm4(ah[mi], stb + 0 * TILE + off);
                ldsm4(al[mi], stb + 1 * TILE + off);
            }
            #pragma unroll
            for (int t = 0; t < NB; t++) {
                uint32_t off = sw64((uint32_t)((b_row + t * 16) * 64 + (b_cb + ks * 2) * 16));
                ldsm4(bfr[t], stb + 2 * TILE + off);
            }
            #pragma unroll
            for (int mi = 0; mi < AM; mi++)
                #pragma unroll
                for (int nj = 0; nj < BN; nj++)
                    mma16816(acc[mi][nj], ah[mi], &bfr[nj >> 1][(nj & 1) * 2]);
            #pragma unroll
            for (int mi = 0; mi < AM; mi++)
                #pragma unroll
                for (int nj = 0; nj < BN; nj++)
                    mma16816(acc[mi][nj], al[mi], &bfr[nj >> 1][(nj & 1) * 2]);
        }
    }
    __syncthreads();
}

#define SMEM_GEMM (3 * 3 * 128 * 64)   // 73728
#define SMEM_SIM  (3 * 3 * 64 * 64)    // 36864

// -------- K0a: fused RMSNorm + fp16 hi/lo split of activations ----
__global__ void k_prepA(const float* __restrict__ x, const float* __restrict__ gamma) {
    const int row = blockIdx.x;
    const int tid = threadIdx.x;
    const float4 v = ((const float4*)(x + (size_t)row * DIM))[tid];
    float s = v.x * v.x + v.y * v.y + v.z * v.z + v.w * v.w;
    #pragma unroll
    for (int o = 16; o; o >>= 1) s += __shfl_xor_sync(0xffffffffu, s, o);
    __shared__ float ws[4];
    __shared__ float rs_sh;
    if ((tid & 31) == 0) ws[tid >> 5] = s;
    __syncthreads();
    if (tid == 0)
        rs_sh = 22.62741699796952f / fmaxf(sqrtf(ws[0] + ws[1] + ws[2] + ws[3]), 1e-12f);
    __syncthreads();
    const float rs = rs_sh;
    const float4 g = ((const float4*)gamma)[tid];
    float a0 = v.x * rs * g.x, a1 = v.y * rs * g.y, a2 = v.z * rs * g.z, a3 = v.w * rs * g.w;
    uint2 ph, pl;
    splith2(a0, a1, ph.x, pl.x);
    splith2(a2, a3, ph.y, pl.y);
    ((uint2*)(g_xhi + (size_t)row * DIM))[tid] = ph;
    ((uint2*)(g_xlo + (size_t)row * DIM))[tid] = pl;
}

// -------- K0b: transpose w_qkv -> [c][k] fp16 --------
__global__ void k_prepW(const float* __restrict__ w) {
    __shared__ float t[32][33];
    const int c0 = blockIdx.x * 32, k0 = blockIdx.y * 32;
    const int tx = threadIdx.x, ty = threadIdx.y;
    #pragma unroll
    for (int i = 0; i < 4; i++)
        t[ty + 8 * i][tx] = w[(size_t)(k0 + ty + 8 * i) * 1536 + c0 + tx];
    __syncthreads();
    #pragma unroll
    for (int i = 0; i < 4; i++) {
        float v = t[tx][ty + 8 * i];
        g_whi[(size_t)(c0 + ty + 8 * i) * 512 + k0 + tx] = __float2half_rn(v);
    }
}

// -------- QKV GEMM: D[m][c] = xn @ w_qkv --------
__global__ __launch_bounds__(256, 2) void k_qkv_mma() {
    extern __shared__ char smem[];
    const int m0 = blockIdx.x * 128;
    const int c0 = blockIdx.y * 128;
    float acc[4][4][4];
    #pragma unroll
    for (int i = 0; i < 4; i++)
        #pragma unroll
        for (int j = 0; j < 4; j++)
            #pragma unroll
            for (int r = 0; r < 4; r++) acc[i][j][r] = 0.f;

    mma_pipe<128, 4, 4, 16>(smem,
                 g_xhi + (size_t)m0 * 512, g_xlo + (size_t)m0 * 512,
                 g_whi + (size_t)c0 * 512, 512, 512, acc);

    const int tid = threadIdx.x;
    const int wid = tid >> 5, lane = tid & 31;
    const int wm = wid >> 2, wn = wid & 3;
    const int b = m0 >> 12;
    const int nbase = (m0 & 4095) + wm * 64 + (lane >> 2);
    const int cloc = wn * 32 + 2 * (lane & 3);
    const int which = c0 >> 9;          // 0:q 1:k 2:v (tile never straddles)
    const int cbase = (c0 & 511) + cloc;

    if (which == 0) {
        __half* dhi = g_qhi + (size_t)b * DINNER * NN;
        __half* dlo = g_qlo + (size_t)b * DINNER * NN;
        #pragma unroll
        for (int mi = 0; mi < 4; mi++)
            #pragma unroll
            for (int nj = 0; nj < 4; nj++) {
                int c = cbase + nj * 8;
                #pragma unroll
                for (int h = 0; h < 2; h++) {
                    int n = nbase + mi * 16 + h * 8;
                    unsigned short h0, l0, h1, l1;
                    splith_s(acc[mi][nj][h * 2], h0, l0);
                    splith_s(acc[mi][nj][h * 2 + 1], h1, l1);
                    *(unsigned short*)(dhi + (size_t)c * NN + n) = h0;
                    *(unsigned short*)(dlo + (size_t)c * NN + n) = l0;
                    *(unsigned short*)(dhi + (size_t)(c + 1) * NN + n) = h1;
                    *(unsigned short*)(dlo + (size_t)(c + 1) * NN + n) = l1;
                }
            }
    } else if (which == 1) {
        __half* dhi = g_khi + (size_t)b * DINNER * NN;
        #pragma unroll
        for (int mi = 0; mi < 4; mi++)
            #pragma unroll
            for (int nj = 0; nj < 4; nj++) {
                int c = cbase + nj * 8;
                #pragma unroll
                for (int h = 0; h < 2; h++) {
                    int n = nbase + mi * 16 + h * 8;
                    *(unsigned short*)(dhi + (size_t)c * NN + n) =
                        (unsigned short)(packh2(acc[mi][nj][h * 2], 0.f) & 0xffff);
                    *(unsigned short*)(dhi + (size_t)(c + 1) * NN + n) =
                        (unsigned short)(packh2(acc[mi][nj][h * 2 + 1], 0.f) & 0xffff);
                }
            }
    } else {
        #pragma unroll
        for (int mi = 0; mi < 4; mi++)
            #pragma unroll
            for (int h = 0; h < 2; h++) {
                int n = nbase + mi * 16 + h * 8;
                size_t base = ((size_t)b * NN + n) * DINNER + cbase;
                #pragma unroll
                for (int nj = 0; nj < 4; nj++) {
                    uint32_t hi, lo;
                    splith2(acc[mi][nj][h * 2], acc[mi][nj][h * 2 + 1], hi, lo);
                    *(uint32_t*)(g_vhi + base + nj * 8) = hi;
                    *(uint32_t*)(g_vlo + base + nj * 8) = lo;
                }
            }
    }
}

// -------- K3: 1/||row|| over n: q from hi+lo, k from hi --------
__global__ void k_rownorm() {
    int row = blockIdx.x;              // 0..8191 (q rows then k rows)
    int r = row & 4095;
    int tid = threadIdx.x;
    float s = 0.f;
    if (row < 4096) {
        const __half* ph = g_qhi + (size_t)r * NN;
        const __half* pl = g_qlo + (size_t)r * NN;
        #pragma unroll
        for (int t = 0; t < 2; t++) {
            int idx = (tid + 256 * t) * 8;
            uint4 vh = *(const uint4*)(ph + idx);
            uint4 vl = *(const uint4*)(pl + idx);
            const uint32_t* hw = &vh.x;
            const uint32_t* lw = &vl.x;
            #pragma unroll
            for (int i = 0; i < 4; i++) {
                float2 h2 = __half22float2(*(const __half2*)&hw[i]);
                float2 l2 = __half22float2(*(const __half2*)&lw[i]);
                float v0 = h2.x + l2.x, v1 = h2.y + l2.y;
                s += v0 * v0 + v1 * v1;
            }
        }
    } else {
        const __half* ph = g_khi + (size_t)r * NN;
        #pragma unroll
        for (int t = 0; t < 2; t++) {
            int idx = (tid + 256 * t) * 8;
            uint4 vh = *(const uint4*)(ph + idx);
            const uint32_t* hw = &vh.x;
            #pragma unroll
            for (int i = 0; i < 4; i++) {
                float2 h2 = __half22float2(*(const __half2*)&hw[i]);
                s += h2.x * h2.x + h2.y * h2.y;
            }
        }
    }
    #pragma unroll
    for (int o = 16; o; o >>= 1) s += __shfl_xor_sync(0xffffffffu, s, o);
    __shared__ float ws[8];
    if ((tid & 31) == 0) ws[tid >> 5] = s;
    __syncthreads();
    if (tid == 0) {
        float t = 0.f;
        #pragma unroll
        for (int i = 0; i < 8; i++) t += ws[i];
        float inv = 1.0f / fmaxf(sqrtf(t), 1e-12f);
        if (row < 4096) g_invnq[row] = inv; else g_invnk[row & 4095] = inv;
    }
}

// -------- K4: sim partials via HMMA over a 512-wide n slice ----
__global__ __launch_bounds__(256) void k_sim_mma() {
    extern __shared__ char smem[];
    const int bh = blockIdx.x;   // 64
    const int sp = blockIdx.y;   // 8 splits of n
    float acc[2][2][4];
    #pragma unroll
    for (int i = 0; i < 2; i++)
        #pragma unroll
        for (int j = 0; j < 2; j++)
            #pragma unroll
            for (int r = 0; r < 4; r++) acc[i][j][r] = 0.f;

    const size_t base = (size_t)bh * DHEAD * NN + sp * 512;
    mma_pipe<64, 2, 2, 16>(smem, g_qhi + base, g_qlo + base,
                           g_khi + base, NN, NN, acc);

    const int tid = threadIdx.x;
    const int wid = tid >> 5, lane = tid & 31;
    const int wm = wid >> 2, wn = wid & 3;
    float* gp = g_gpart + ((size_t)bh * 8 + sp) * 4096;
    #pragma unroll
    for (int mi = 0; mi < 2; mi++)
        #pragma unroll
        for (int h = 0; h < 2; h++) {
            int d = wm * 32 + mi * 16 + (lane >> 2) + h * 8;
            #pragma unroll
            for (int nj = 0; nj < 2; nj++) {
                int e = wn * 16 + nj * 8 + 2 * (lane & 3);
                *(float2*)(gp + d * 64 + e) =
                    make_float2(acc[mi][nj][h * 2], acc[mi][nj][h * 2 + 1]);
            }
        }
}

// -------- K5: reduce + scale + softmax --------
__global__ void k_softmax(const float* __restrict__ temperature) {
    const int bh = blockIdx.x;
    const int d = threadIdx.x;
    const int hh = bh & 7;
    const float sc = 8.0f * expf(temperature[hh]) * g_invnq[bh * 64 + d];
    const float* gp = g_gpart + (size_t)bh * 8 * 4096;
    float vals[64];
    float mx = -1e30f;
    #pragma unroll 4
    for (int e = 0; e < 64; e++) {
        float s = 0.f;
        #pragma unroll
        for (int sp = 0; sp < 8; sp++) s += gp[sp * 4096 + d * 64 + e];
        s *= sc * g_invnk[bh * 64 + e];
        vals[e] = s;
        mx = fmaxf(mx, s);
    }
    float sum = 0.f;
    #pragma unroll 4
    for (int e = 0; e < 64; e++) { vals[e] = expf(vals[e] - mx); sum += vals[e]; }
    const float inv = 1.0f / sum;
    #pragma unroll 4
    for (int e = 0; e < 64; e++)
        g_attn[(size_t)bh * 4096 + d * 64 + e] = vals[e] * inv;
}

// -------- K6: fold attn into w_out, write transposed fp16 [b][j][c] --------
__global__ __launch_bounds__(256) void k_attnw(const float* __restrict__ w_out) {
    const int bh = blockIdx.x;
    const int jt = blockIdx.y;
    const int b = bh >> 3, hh = bh & 7;
    __shared__ float As[64][64];
    const int tid = threadIdx.x;
    #pragma unroll
    for (int t = 0; t < 16; t++) {
        int idx = tid + 256 * t;
        As[idx >> 6][idx & 63] = g_attn[(size_t)bh * 4096 + idx];
    }
    __syncthreads();
    const int j = jt * 128 + (tid & 127);
    const int e0 = (tid >> 7) * 32;
    float acc[32];
    #pragma unroll
    for (int i = 0; i < 32; i++) acc[i] = 0.f;
    for (int d = 0; d < 64; d++) {
        float w = w_out[(hh * 64 + d) * DIM + j];
        #pragma unroll
        for (int i = 0; i < 32; i++) acc[i] += As[d][e0 + i] * w;
    }
    size_t base = ((size_t)b * 512 + j) * 512 + hh * 64 + e0;
    #pragma unroll
    for (int i = 0; i < 32; i++)
        g_awhi[base + i] = __float2half_rn(acc[i]);
}

// -------- final GEMM: out[b][n][j] = sum_c V[b][n][c] * aw[b][j][c] --------
__global__ __launch_bounds__(256, 2) void k_final_mma(float* __restrict__ out) {
    extern __shared__ char smem[];
    const int m0 = blockIdx.x * 128;   // n
    const int j0 = blockIdx.y * 128;   // j
    const int b = blockIdx.z;
    float acc[4][4][4];
    #pragma unroll
    for (int i = 0; i < 4; i++)
        #pragma unroll
        for (int j = 0; j < 4; j++)
            #pragma unroll
            for (int r = 0; r < 4; r++) acc[i][j][r] = 0.f;

    mma_pipe<128, 4, 4, 16>(smem,
                 g_vhi + ((size_t)b * NN + m0) * 512, g_vlo + ((size_t)b * NN + m0) * 512,
                 g_awhi + ((size_t)b * 512 + j0) * 512, 512, 512, acc);

    const int tid = threadIdx.x;
    const int wid = tid >> 5, lane = tid & 31;
    const int wm = wid >> 2, wn = wid & 3;
    const int nbase = m0 + wm * 64 + (lane >> 2);
    const int jbase = j0 + wn * 32 + 2 * (lane & 3);
    #pragma unroll
    for (int mi = 0; mi < 4; mi++)
        #pragma unroll
        for (int h = 0; h < 2; h++) {
            int n = nbase + mi * 16 + h * 8;
            float* orow = out + ((size_t)b * NN + n) * DIM + jbase;
            #pragma unroll
            for (int nj = 0; nj < 4; nj++) {
                float2 v = make_float2(acc[mi][nj][h * 2], acc[mi][nj][h * 2 + 1]);
                *(float2*)(orow + nj * 8) = v;
            }
        }
}

// -------- launch --------
extern "C" void kernel_launch(void* const* d_in, const int* in_sizes, int n_in,
                              void* d_out, int out_size) {
    const float* x           = (const float*)d_in[0];
    const float* gamma       = (const float*)d_in[1];
    const float* w_qkv       = (const float*)d_in[2];
    const float* temperature = (const float*)d_in[3];
    const float* w_out       = (const float*)d_in[4];
    float* out = (float*)d_out;

    static int attr_done = 0;
    if (!attr_done) {
        cudaFuncSetAttribute(k_qkv_mma, cudaFuncAttributeMaxDynamicSharedMemorySize, SMEM_GEMM);
        cudaFuncSetAttribute(k_final_mma, cudaFuncAttributeMaxDynamicSharedMemorySize, SMEM_GEMM);
        cudaFuncSetAttribute(k_sim_mma, cudaFuncAttributeMaxDynamicSharedMemorySize, SMEM_SIM);
        attr_done = 1;
    }

    k_prepA    <<<BB * NN, 128>>>(x, gamma);
    k_prepW    <<<dim3(48, 16), dim3(32, 8)>>>(w_qkv);
    k_qkv_mma  <<<dim3(256, 12), 256, SMEM_GEMM>>>();
    k_rownorm  <<<2 * BH * DHEAD, 256>>>();
    k_sim_mma  <<<dim3(BH, 8), 256, SMEM_SIM>>>();
    k_softmax  <<<BH, 64>>>(temperature);
    k_attnw    <<<dim3(BH, 4), 256>>>(w_out);
    k_final_mma<<<dim3(32, 4, BB), 256, SMEM_GEMM>>>(out);
}

// round 10
// speedup vs baseline: 4.8252x; 1.1862x over previous
#include <cuda_runtime.h>
#include <cuda_fp16.h>
#include <math.h>
#include <stdint.h>

#define BB 8
#define NN 4096
#define DIM 512
#define HEADS 8
#define DHEAD 64
#define DINNER 512
#define BH (BB*HEADS)       // 64

// ---------------- scratch (static device globals) ----------------
__device__ __half g_qhi[(size_t)BB*DINNER*NN]; // [b][hd][n]
__device__ __half g_qlo[(size_t)BB*DINNER*NN];
__device__ __half g_khi[(size_t)BB*DINNER*NN]; // hi only (B side of sim)
__device__ __half g_vhi[(size_t)BB*NN*DINNER]; // [b][n][c]
__device__ __half g_vlo[(size_t)BB*NN*DINNER];
__device__ __half g_xhi[(size_t)BB*NN*DIM];    // normalized x, [m][k]
__device__ __half g_xlo[(size_t)BB*NN*DIM];
__device__ __half g_whi[1536*DIM];             // w_qkv^T, [c][k]  (hi only)
__device__ __half g_awhi[(size_t)BB*DIM*DINNER]; // attn-folded w_out^T, [b][j][c]
__device__ float g_invnq[BH*DHEAD];
__device__ float g_invnk[BH*DHEAD];
__device__ float g_gpart[BH*8*DHEAD*DHEAD];
__device__ float g_attn[BH*DHEAD*DHEAD];

// ---------------- helpers ----------------
__device__ __forceinline__ uint32_t smem_u32(const void* p) {
    uint32_t a;
    asm("{ .reg .u64 t; cvta.to.shared.u64 t, %1; cvt.u32.u64 %0, t; }" : "=r"(a) : "l"(p));
    return a;
}
// swizzle for 64B rows (32 fp16)
__device__ __forceinline__ uint32_t sw64(uint32_t o) { return o ^ ((o >> 3) & 0x30); }

__device__ __forceinline__ void ldsm4(uint32_t* r, uint32_t addr) {
    asm volatile("ldmatrix.sync.aligned.m8n8.x4.shared.b16 {%0,%1,%2,%3}, [%4];"
                 : "=r"(r[0]), "=r"(r[1]), "=r"(r[2]), "=r"(r[3]) : "r"(addr));
}
__device__ __forceinline__ void mma16816(float* d, const uint32_t* a, const uint32_t* b) {
    asm volatile("mma.sync.aligned.m16n8k16.row.col.f32.f16.f16.f32 "
                 "{%0,%1,%2,%3}, {%4,%5,%6,%7}, {%8,%9}, {%0,%1,%2,%3};"
                 : "+f"(d[0]), "+f"(d[1]), "+f"(d[2]), "+f"(d[3])
                 : "r"(a[0]), "r"(a[1]), "r"(a[2]), "r"(a[3]), "r"(b[0]), "r"(b[1]));
}
__device__ __forceinline__ void cpasync16(uint32_t dst, const void* src) {
    asm volatile("cp.async.cg.shared.global [%0], [%1], 16;" :: "r"(dst), "l"(src) : "memory");
}
#define CP_COMMIT() asm volatile("cp.async.commit_group;" ::: "memory")
#define CP_WAIT1()  asm volatile("cp.async.wait_group 1;" ::: "memory")
#define CP_WAIT0()  asm volatile("cp.async.wait_group 0;" ::: "memory")

__device__ __forceinline__ void splith_s(float v, unsigned short& h, unsigned short& l) {
    __half hh = __float2half_rn(v);
    __half ll = __float2half_rn(v - __half2float(hh));
    h = *reinterpret_cast<unsigned short*>(&hh);
    l = *reinterpret_cast<unsigned short*>(&ll);
}
__device__ __forceinline__ void splith2(float a, float b, uint32_t& hi, uint32_t& lo) {
    unsigned short h0, l0, h1, l1;
    splith_s(a, h0, l0);
    splith_s(b, h1, l1);
    hi = (uint32_t)h0 | ((uint32_t)h1 << 16);
    lo = (uint32_t)l0 | ((uint32_t)l1 << 16);
}
__device__ __forceinline__ unsigned short packh(float a) {
    __half h = __float2half_rn(a);
    return *reinterpret_cast<unsigned short*>(&h);
}

// ======= 3-stage pipelined fp16 MMA mainloop =======
// warp grid 2(m) x 4(n); warp tile (AM*16) x (BN*8); K chunks of 32.
// TERMS==2: D += Ahi*Bhi^T + Alo*Bhi^T  (A fp16-split); TERMS==1: hi only.
template<int ROWS, int AM, int BN, int NCH, int TERMS>
__device__ __forceinline__ void mma_pipe(char* smem,
        const __half* __restrict__ Ahi, const __half* __restrict__ Alo,
        const __half* __restrict__ Bhi,
        int ldA, int ldB, float (*acc)[BN][4]) {
    const int tid = threadIdx.x;
    const int wid = tid >> 5, lane = tid & 31;
    const int wm = wid >> 2, wn = wid & 3;
    const int g = lane >> 3, lr = lane & 7;
    const uint32_t sb = smem_u32(smem);
    constexpr int TILE = ROWS * 64;        // bytes per tile (32 fp16/row)
    constexpr int STAGE = 3 * TILE;
    constexpr int LIT = (ROWS * 4) / 256;  // 16B-chunks per thread per tile
    constexpr int NB = (BN + 1) / 2;
    const int a_row = wm * (AM * 16) + lr + (g & 1) * 8;
    const int a_cb = (g >> 1);
    const int b_row = wn * (BN * 8) + lr + (g >> 1) * 8;
    const int b_cb = (g & 1);

    auto issue = [&](int ch, int st) {
        uint32_t base = sb + st * STAGE;
        #pragma unroll
        for (int i = 0; i < LIT; i++) {
            int idx = tid + 256 * i;
            int row = idx >> 2, c = idx & 3;
            uint32_t so = sw64((uint32_t)(row * 64 + c * 16));
            int col = ch * 32 + c * 8;
            cpasync16(base + 0 * TILE + so, Ahi + (size_t)row * ldA + col);
            if (TERMS == 2)
                cpasync16(base + 1 * TILE + so, Alo + (size_t)row * ldA + col);
            cpasync16(base + 2 * TILE + so, Bhi + (size_t)row * ldB + col);
        }
    };

    issue(0, 0); CP_COMMIT();
    issue(1, 1); CP_COMMIT();
    for (int ch = 0; ch < NCH; ch++) {
        if (ch < NCH - 1) { CP_WAIT1(); } else { CP_WAIT0(); }
        __syncthreads();
        if (ch + 2 < NCH) { issue(ch + 2, (ch + 2) % 3); CP_COMMIT(); }
        uint32_t stb = sb + (ch % 3) * STAGE;
        #pragma unroll
        for (int ks = 0; ks < 2; ks++) {
            uint32_t ah[AM][4], al[AM][4], bfr[NB][4];
            #pragma unroll
            for (int mi = 0; mi < AM; mi++) {
                uint32_t off = sw64((uint32_t)((a_row + mi * 16) * 64 + (a_cb + ks * 2) * 16));
                ldsm4(ah[mi], stb + 0 * TILE + off);
                if (TERMS == 2) ldsm4(al[mi], stb + 1 * TILE + off);
            }
            #pragma unroll
            for (int t = 0; t < NB; t++) {
                uint32_t off = sw64((uint32_t)((b_row + t * 16) * 64 + (b_cb + ks * 2) * 16));
                ldsm4(bfr[t], stb + 2 * TILE + off);
            }
            #pragma unroll
            for (int mi = 0; mi < AM; mi++)
                #pragma unroll
                for (int nj = 0; nj < BN; nj++)
                    mma16816(acc[mi][nj], ah[mi], &bfr[nj >> 1][(nj & 1) * 2]);
            if (TERMS == 2) {
                #pragma unroll
                for (int mi = 0; mi < AM; mi++)
                    #pragma unroll
                    for (int nj = 0; nj < BN; nj++)
                        mma16816(acc[mi][nj], al[mi], &bfr[nj >> 1][(nj & 1) * 2]);
            }
        }
    }
    __syncthreads();
}

#define SMEM_GEMM (3 * 3 * 128 * 64)   // 73728
#define SMEM_SIM  (3 * 3 * 64 * 64)    // 36864

// -------- K0a: fused RMSNorm + fp16 hi/lo split of activations ----
__global__ void k_prepA(const float* __restrict__ x, const float* __restrict__ gamma) {
    const int row = blockIdx.x;
    const int tid = threadIdx.x;
    const float4 v = ((const float4*)(x + (size_t)row * DIM))[tid];
    float s = v.x * v.x + v.y * v.y + v.z * v.z + v.w * v.w;
    #pragma unroll
    for (int o = 16; o; o >>= 1) s += __shfl_xor_sync(0xffffffffu, s, o);
    __shared__ float ws[4];
    __shared__ float rs_sh;
    if ((tid & 31) == 0) ws[tid >> 5] = s;
    __syncthreads();
    if (tid == 0)
        rs_sh = 22.62741699796952f / fmaxf(sqrtf(ws[0] + ws[1] + ws[2] + ws[3]), 1e-12f);
    __syncthreads();
    const float rs = rs_sh;
    const float4 g = ((const float4*)gamma)[tid];
    float a0 = v.x * rs * g.x, a1 = v.y * rs * g.y, a2 = v.z * rs * g.z, a3 = v.w * rs * g.w;
    uint2 ph, pl;
    splith2(a0, a1, ph.x, pl.x);
    splith2(a2, a3, ph.y, pl.y);
    ((uint2*)(g_xhi + (size_t)row * DIM))[tid] = ph;
    ((uint2*)(g_xlo + (size_t)row * DIM))[tid] = pl;
}

// -------- K0b: transpose w_qkv -> [c][k] fp16 --------
__global__ void k_prepW(const float* __restrict__ w) {
    __shared__ float t[32][33];
    const int c0 = blockIdx.x * 32, k0 = blockIdx.y * 32;
    const int tx = threadIdx.x, ty = threadIdx.y;
    #pragma unroll
    for (int i = 0; i < 4; i++)
        t[ty + 8 * i][tx] = w[(size_t)(k0 + ty + 8 * i) * 1536 + c0 + tx];
    __syncthreads();
    #pragma unroll
    for (int i = 0; i < 4; i++) {
        float v = t[tx][ty + 8 * i];
        g_whi[(size_t)(c0 + ty + 8 * i) * 512 + k0 + tx] = __float2half_rn(v);
    }
}

// -------- QKV GEMM: D[m][c] = xn @ w_qkv --------
// q tiles (which==0): 2-term; k/v tiles: 1-term (their downstream error floor
// is already fp16-rounding level).
__global__ __launch_bounds__(256, 2) void k_qkv_mma() {
    extern __shared__ char smem[];
    const int m0 = blockIdx.x * 128;
    const int c0 = blockIdx.y * 128;
    const int which = c0 >> 9;          // 0:q 1:k 2:v (tile never straddles)
    float acc[4][4][4];
    #pragma unroll
    for (int i = 0; i < 4; i++)
        #pragma unroll
        for (int j = 0; j < 4; j++)
            #pragma unroll
            for (int r = 0; r < 4; r++) acc[i][j][r] = 0.f;

    if (which == 0)
        mma_pipe<128, 4, 4, 16, 2>(smem,
                     g_xhi + (size_t)m0 * 512, g_xlo + (size_t)m0 * 512,
                     g_whi + (size_t)c0 * 512, 512, 512, acc);
    else
        mma_pipe<128, 4, 4, 16, 1>(smem,
                     g_xhi + (size_t)m0 * 512, g_xlo + (size_t)m0 * 512,
                     g_whi + (size_t)c0 * 512, 512, 512, acc);

    const int tid = threadIdx.x;
    const int wid = tid >> 5, lane = tid & 31;
    const int wm = wid >> 2, wn = wid & 3;
    const int b = m0 >> 12;
    const int nbase = (m0 & 4095) + wm * 64 + (lane >> 2);
    const int cloc = wn * 32 + 2 * (lane & 3);
    const int cbase = (c0 & 511) + cloc;

    if (which == 0) {
        __half* dhi = g_qhi + (size_t)b * DINNER * NN;
        __half* dlo = g_qlo + (size_t)b * DINNER * NN;
        #pragma unroll
        for (int mi = 0; mi < 4; mi++)
            #pragma unroll
            for (int nj = 0; nj < 4; nj++) {
                int c = cbase + nj * 8;
                #pragma unroll
                for (int h = 0; h < 2; h++) {
                    int n = nbase + mi * 16 + h * 8;
                    unsigned short h0, l0, h1, l1;
                    splith_s(acc[mi][nj][h * 2], h0, l0);
                    splith_s(acc[mi][nj][h * 2 + 1], h1, l1);
                    *(unsigned short*)(dhi + (size_t)c * NN + n) = h0;
                    *(unsigned short*)(dlo + (size_t)c * NN + n) = l0;
                    *(unsigned short*)(dhi + (size_t)(c + 1) * NN + n) = h1;
                    *(unsigned short*)(dlo + (size_t)(c + 1) * NN + n) = l1;
                }
            }
    } else if (which == 1) {
        __half* dhi = g_khi + (size_t)b * DINNER * NN;
        #pragma unroll
        for (int mi = 0; mi < 4; mi++)
            #pragma unroll
            for (int nj = 0; nj < 4; nj++) {
                int c = cbase + nj * 8;
                #pragma unroll
                for (int h = 0; h < 2; h++) {
                    int n = nbase + mi * 16 + h * 8;
                    *(unsigned short*)(dhi + (size_t)c * NN + n) = packh(acc[mi][nj][h * 2]);
                    *(unsigned short*)(dhi + (size_t)(c + 1) * NN + n) = packh(acc[mi][nj][h * 2 + 1]);
                }
            }
    } else {
        #pragma unroll
        for (int mi = 0; mi < 4; mi++)
            #pragma unroll
            for (int h = 0; h < 2; h++) {
                int n = nbase + mi * 16 + h * 8;
                size_t base = ((size_t)b * NN + n) * DINNER + cbase;
                #pragma unroll
                for (int nj = 0; nj < 4; nj++) {
                    uint32_t hi, lo;
                    splith2(acc[mi][nj][h * 2], acc[mi][nj][h * 2 + 1], hi, lo);
                    *(uint32_t*)(g_vhi + base + nj * 8) = hi;
                    *(uint32_t*)(g_vlo + base + nj * 8) = lo;
                }
            }
    }
}

// -------- K3: 1/||row|| over n: q from hi+lo, k from hi --------
__global__ void k_rownorm() {
    int row = blockIdx.x;              // 0..8191 (q rows then k rows)
    int r = row & 4095;
    int tid = threadIdx.x;
    float s = 0.f;
    if (row < 4096) {
        const __half* ph = g_qhi + (size_t)r * NN;
        const __half* pl = g_qlo + (size_t)r * NN;
        #pragma unroll
        for (int t = 0; t < 2; t++) {
            int idx = (tid + 256 * t) * 8;
            uint4 vh = *(const uint4*)(ph + idx);
            uint4 vl = *(const uint4*)(pl + idx);
            const uint32_t* hw = &vh.x;
            const uint32_t* lw = &vl.x;
            #pragma unroll
            for (int i = 0; i < 4; i++) {
                float2 h2 = __half22float2(*(const __half2*)&hw[i]);
                float2 l2 = __half22float2(*(const __half2*)&lw[i]);
                float v0 = h2.x + l2.x, v1 = h2.y + l2.y;
                s += v0 * v0 + v1 * v1;
            }
        }
    } else {
        const __half* ph = g_khi + (size_t)r * NN;
        #pragma unroll
        for (int t = 0; t < 2; t++) {
            int idx = (tid + 256 * t) * 8;
            uint4 vh = *(const uint4*)(ph + idx);
            const uint32_t* hw = &vh.x;
            #pragma unroll
            for (int i = 0; i < 4; i++) {
                float2 h2 = __half22float2(*(const __half2*)&hw[i]);
                s += h2.x * h2.x + h2.y * h2.y;
            }
        }
    }
    #pragma unroll
    for (int o = 16; o; o >>= 1) s += __shfl_xor_sync(0xffffffffu, s, o);
    __shared__ float ws[8];
    if ((tid & 31) == 0) ws[tid >> 5] = s;
    __syncthreads();
    if (tid == 0) {
        float t = 0.f;
        #pragma unroll
        for (int i = 0; i < 8; i++) t += ws[i];
        float inv = 1.0f / fmaxf(sqrtf(t), 1e-12f);
        if (row < 4096) g_invnq[row] = inv; else g_invnk[row & 4095] = inv;
    }
}

// -------- K4: sim partials via HMMA over a 512-wide n slice ----
__global__ __launch_bounds__(256) void k_sim_mma() {
    extern __shared__ char smem[];
    const int bh = blockIdx.x;   // 64
    const int sp = blockIdx.y;   // 8 splits of n
    float acc[2][2][4];
    #pragma unroll
    for (int i = 0; i < 2; i++)
        #pragma unroll
        for (int j = 0; j < 2; j++)
            #pragma unroll
            for (int r = 0; r < 4; r++) acc[i][j][r] = 0.f;

    const size_t base = (size_t)bh * DHEAD * NN + sp * 512;
    mma_pipe<64, 2, 2, 16, 2>(smem, g_qhi + base, g_qlo + base,
                              g_khi + base, NN, NN, acc);

    const int tid = threadIdx.x;
    const int wid = tid >> 5, lane = tid & 31;
    const int wm = wid >> 2, wn = wid & 3;
    float* gp = g_gpart + ((size_t)bh * 8 + sp) * 4096;
    #pragma unroll
    for (int mi = 0; mi < 2; mi++)
        #pragma unroll
        for (int h = 0; h < 2; h++) {
            int d = wm * 32 + mi * 16 + (lane >> 2) + h * 8;
            #pragma unroll
            for (int nj = 0; nj < 2; nj++) {
                int e = wn * 16 + nj * 8 + 2 * (lane & 3);
                *(float2*)(gp + d * 64 + e) =
                    make_float2(acc[mi][nj][h * 2], acc[mi][nj][h * 2 + 1]);
            }
        }
}

// -------- K5: reduce + scale + softmax --------
__global__ void k_softmax(const float* __restrict__ temperature) {
    const int bh = blockIdx.x;
    const int d = threadIdx.x;
    const int hh = bh & 7;
    const float sc = 8.0f * expf(temperature[hh]) * g_invnq[bh * 64 + d];
    const float* gp = g_gpart + (size_t)bh * 8 * 4096;
    float vals[64];
    float mx = -1e30f;
    #pragma unroll 4
    for (int e = 0; e < 64; e++) {
        float s = 0.f;
        #pragma unroll
        for (int sp = 0; sp < 8; sp++) s += gp[sp * 4096 + d * 64 + e];
        s *= sc * g_invnk[bh * 64 + e];
        vals[e] = s;
        mx = fmaxf(mx, s);
    }
    float sum = 0.f;
    #pragma unroll 4
    for (int e = 0; e < 64; e++) { vals[e] = expf(vals[e] - mx); sum += vals[e]; }
    const float inv = 1.0f / sum;
    #pragma unroll 4
    for (int e = 0; e < 64; e++)
        g_attn[(size_t)bh * 4096 + d * 64 + e] = vals[e] * inv;
}

// -------- K6: fold attn into w_out, write transposed fp16 [b][j][c] --------
__global__ __launch_bounds__(256) void k_attnw(const float* __restrict__ w_out) {
    const int bh = blockIdx.x;
    const int jt = blockIdx.y;
    const int b = bh >> 3, hh = bh & 7;
    __shared__ float As[64][64];
    const int tid = threadIdx.x;
    #pragma unroll
    for (int t = 0; t < 16; t++) {
        int idx = tid + 256 * t;
        As[idx >> 6][idx & 63] = g_attn[(size_t)bh * 4096 + idx];
    }
    __syncthreads();
    const int j = jt * 128 + (tid & 127);
    const int e0 = (tid >> 7) * 32;
    float acc[32];
    #pragma unroll
    for (int i = 0; i < 32; i++) acc[i] = 0.f;
    for (int d = 0; d < 64; d++) {
        float w = w_out[(hh * 64 + d) * DIM + j];
        #pragma unroll
        for (int i = 0; i < 32; i++) acc[i] += As[d][e0 + i] * w;
    }
    size_t base = ((size_t)b * 512 + j) * 512 + hh * 64 + e0;
    #pragma unroll
    for (int i = 0; i < 32; i++)
        g_awhi[base + i] = __float2half_rn(acc[i]);
}

// -------- final GEMM: out[b][n][j] = sum_c V[b][n][c] * aw[b][j][c] --------
__global__ __launch_bounds__(256, 2) void k_final_mma(float* __restrict__ out) {
    extern __shared__ char smem[];
    const int m0 = blockIdx.x * 128;   // n
    const int j0 = blockIdx.y * 128;   // j
    const int b = blockIdx.z;
    float acc[4][4][4];
    #pragma unroll
    for (int i = 0; i < 4; i++)
        #pragma unroll
        for (int j = 0; j < 4; j++)
            #pragma unroll
            for (int r = 0; r < 4; r++) acc[i][j][r] = 0.f;

    mma_pipe<128, 4, 4, 16, 2>(smem,
                 g_vhi + ((size_t)b * NN + m0) * 512, g_vlo + ((size_t)b * NN + m0) * 512,
                 g_awhi + ((size_t)b * 512 + j0) * 512, 512, 512, acc);

    const int tid = threadIdx.x;
    const int wid = tid >> 5, lane = tid & 31;
    const int wm = wid >> 2, wn = wid & 3;
    const int nbase = m0 + wm * 64 + (lane >> 2);
    const int jbase = j0 + wn * 32 + 2 * (lane & 3);
    #pragma unroll
    for (int mi = 0; mi < 4; mi++)
        #pragma unroll
        for (int h = 0; h < 2; h++) {
            int n = nbase + mi * 16 + h * 8;
            float* orow = out + ((size_t)b * NN + n) * DIM + jbase;
            #pragma unroll
            for (int nj = 0; nj < 4; nj++) {
                float2 v = make_float2(acc[mi][nj][h * 2], acc[mi][nj][h * 2 + 1]);
                *(float2*)(orow + nj * 8) = v;
            }
        }
}

// -------- launch --------
extern "C" void kernel_launch(void* const* d_in, const int* in_sizes, int n_in,
                              void* d_out, int out_size) {
    const float* x           = (const float*)d_in[0];
    const float* gamma       = (const float*)d_in[1];
    const float* w_qkv       = (const float*)d_in[2];
    const float* temperature = (const float*)d_in[3];
    const float* w_out       = (const float*)d_in[4];
    float* out = (float*)d_out;

    static int attr_done = 0;
    if (!attr_done) {
        cudaFuncSetAttribute(k_qkv_mma, cudaFuncAttributeMaxDynamicSharedMemorySize, SMEM_GEMM);
        cudaFuncSetAttribute(k_final_mma, cudaFuncAttributeMaxDynamicSharedMemorySize, SMEM_GEMM);
        cudaFuncSetAttribute(k_sim_mma, cudaFuncAttributeMaxDynamicSharedMemorySize, SMEM_SIM);
        attr_done = 1;
    }

    k_prepA    <<<BB * NN, 128>>>(x, gamma);
    k_prepW    <<<dim3(48, 16), dim3(32, 8)>>>(w_qkv);
    k_qkv_mma  <<<dim3(256, 12), 256, SMEM_GEMM>>>();
    k_rownorm  <<<2 * BH * DHEAD, 256>>>();
    k_sim_mma  <<<dim3(BH, 8), 256, SMEM_SIM>>>();
    k_softmax  <<<BH, 64>>>(temperature);
    k_attnw    <<<dim3(BH, 4), 256>>>(w_out);
    k_final_mma<<<dim3(32, 4, BB), 256, SMEM_GEMM>>>(out);
}